// round 13
// baseline (speedup 1.0000x reference)
#include <cuda_runtime.h>
#include <cuda_fp16.h>
#include <math.h>
#include <stdint.h>

#define HID   1024
#define OUTD  768
#define BATCH 256
#define TMAX  256
#define NJB   (HID / 32)

// ===========================================================================
// helpers
// ===========================================================================
__device__ __forceinline__ uint32_t smem_u32(const void* p) {
    uint32_t a;
    asm("{ .reg .u64 t; cvta.to.shared.u64 t, %1; cvt.u32.u64 %0, t; }" : "=r"(a) : "l"(p));
    return a;
}
__device__ __host__ __forceinline__ uint32_t sw128(uint32_t off) {
    return off ^ ((off >> 3) & 0x70);
}
__device__ __forceinline__ void cpa16(uint32_t dst, const void* src) {
    asm volatile("cp.async.cg.shared.global [%0], [%1], 16;" :: "r"(dst), "l"(src));
}
#define CP_COMMIT() asm volatile("cp.async.commit_group;" ::: "memory")
#define CP_WAIT(n)  asm volatile("cp.async.wait_group %0;" :: "n"(n) : "memory")

__device__ __forceinline__ void ldsm4(uint32_t (&r)[4], uint32_t addr) {
    asm volatile("ldmatrix.sync.aligned.m8n8.x4.shared.b16 {%0,%1,%2,%3}, [%4];"
        : "=r"(r[0]), "=r"(r[1]), "=r"(r[2]), "=r"(r[3]) : "r"(addr));
}
__device__ __forceinline__ void mma16816h(float (&d)[4], const uint32_t (&a)[4],
                                          uint32_t b0, uint32_t b1) {
    asm volatile("mma.sync.aligned.m16n8k16.row.col.f32.f16.f16.f32 "
        "{%0,%1,%2,%3}, {%4,%5,%6,%7}, {%8,%9}, {%0,%1,%2,%3};"
        : "+f"(d[0]), "+f"(d[1]), "+f"(d[2]), "+f"(d[3])
        : "r"(a[0]), "r"(a[1]), "r"(a[2]), "r"(a[3]), "r"(b0), "r"(b1));
}

// release/acquire sync primitives (tid0/lane-level; bar.sync carries CTA-local HB)
__device__ __forceinline__ unsigned atom_add_release(unsigned* p, unsigned v) {
    unsigned old;
    asm volatile("atom.release.gpu.global.add.u32 %0, [%1], %2;"
        : "=r"(old) : "l"(p), "r"(v) : "memory");
    return old;
}
__device__ __forceinline__ unsigned ld_acquire(const unsigned* p) {
    unsigned v;
    asm volatile("ld.acquire.gpu.global.u32 %0, [%1];" : "=r"(v) : "l"(p) : "memory");
    return v;
}

// ===========================================================================
// device scratch
// ===========================================================================
__device__ float g_H[2 * BATCH * HID];          // slot0 = h_0, slot1 = h_1
__device__ float g_Wih_f[NJB * OUTD * 3 * 32];
__device__ float g_Whh_f[NJB * HID * 3 * 32];
__device__ float g_Wc[3 * HID * HID];
__device__ float g_bcomb[3 * HID];
__device__ unsigned g_barm8[2][8 * 32];         // per-mh, slot (nt>>3) producer progress
__device__ unsigned g_outq;
// fp16 SW128 tile images
__device__ __align__(1024) char g_Aimg[(size_t)(TMAX + 1) * 2 * 16 * 16384]; // [t][mh][kc] 128x64 fp16
__device__ __align__(1024) char g_Wimg[(size_t)64 * 16 * 8192];              // fused single-fp16 [nt][kc]
__device__ __align__(1024) char g_Wfcimg[(size_t)6 * 16 * 32768];            // [nt][kc]{hi16K,lo16K}

// ===========================================================================
// fp32 SIMT pieces (step 0 + W_comb precompute)
// ===========================================================================
__device__ __forceinline__ unsigned long long dup2(float x) {
    unsigned long long r;
    asm("mov.b64 %0, {%1, %1};" : "=l"(r) : "f"(x));
    return r;
}
__device__ __forceinline__ void fmax2(unsigned long long& d, unsigned long long a,
                                      unsigned long long b) {
    asm("fma.rn.f32x2 %0, %1, %2, %0;" : "+l"(d) : "l"(a), "l"(b));
}
union F4U { float4 f; unsigned long long u[2]; };
union U2F { unsigned long long u; float2 f; };
__device__ __forceinline__ float sigmf(float x) { return 1.0f / (1.0f + __expf(-x)); }

__global__ __launch_bounds__(256) void pack_w(float* __restrict__ dst,
                                              const float* __restrict__ src, int Ks) {
    __shared__ float sm[32][33];
    int k0 = blockIdx.x * 32, jb = blockIdx.y, g = blockIdx.z, t = threadIdx.x;
    int jl = t >> 3, kq = t & 7;
    float4 v = *(const float4*)(src + (size_t)(g * HID + jb * 32 + jl) * Ks + k0 + kq * 4);
    sm[jl][kq * 4 + 0] = v.x; sm[jl][kq * 4 + 1] = v.y;
    sm[jl][kq * 4 + 2] = v.z; sm[jl][kq * 4 + 3] = v.w;
    __syncthreads();
    int ji = t & 31, kk0 = t >> 5;
#pragma unroll
    for (int r = 0; r < 4; r++) {
        int kk = kk0 + r * 8;
        dst[(((size_t)jb * Ks + k0 + kk) * 3 + g) * 32 + ji] = sm[ji][kk];
    }
}

__global__ __launch_bounds__(256) void bcomb_k(const float* __restrict__ Wih,
                                               const float* __restrict__ bfc,
                                               const float* __restrict__ bih,
                                               float* __restrict__ out) {
    int j = blockIdx.x * 8 + (threadIdx.x >> 5);
    int lane = threadIdx.x & 31;
    float s = 0.f;
    for (int o = lane; o < OUTD; o += 32) s += Wih[(size_t)j * OUTD + o] * bfc[o];
#pragma unroll
    for (int off = 16; off; off >>= 1) s += __shfl_xor_sync(0xffffffffu, s, off);
    if (lane == 0) out[j] = s + bih[j];
}

__global__ __launch_bounds__(256) void copy_f(float* __restrict__ dst,
                                              const float* __restrict__ src, int n4) {
    int i = blockIdx.x * 256 + threadIdx.x;
    if (i < n4) ((float4*)dst)[i] = ((const float4*)src)[i];
}

__global__ void init_sync() {
    for (int m = 0; m < 2; m++)
        for (int s = 0; s < 8; s++) g_barm8[m][s * 32] = 0;
    g_outq = 0;
}

__global__ __launch_bounds__(256) void gemm_nn(const float* __restrict__ A,
                                               const float* __restrict__ B,
                                               const float* __restrict__ bias,
                                               float* __restrict__ C,
                                               int M, int N, int K) {
    __shared__ float2 sA[32][66];
    __shared__ float  sB[32][64];
    int n0 = blockIdx.x * 64, m0 = blockIdx.y * 128, t = threadIdx.x;
    int tn = t & 15, tm = t >> 4;
    unsigned long long acc[4][4] = {};
    float4 ast[4], bst[2];
#pragma unroll
    for (int r = 0; r < 4; r++) {
        int idx = t + 256 * r, m = idx >> 3, kf = idx & 7;
        ast[r] = *(const float4*)(A + (size_t)(m0 + m) * K + kf * 4);
    }
#pragma unroll
    for (int r = 0; r < 2; r++) {
        int idx = t + 256 * r, kk = idx >> 4, nf = idx & 15;
        bst[r] = *(const float4*)(B + (size_t)kk * N + n0 + nf * 4);
    }
    int nch = K >> 5;
    for (int ch = 0; ch < nch; ch++) {
        float* sp = (float*)&sA[0][0];
#pragma unroll
        for (int r = 0; r < 4; r++) {
            int idx = t + 256 * r, m = idx >> 3, kf = idx & 7;
            sp[(kf * 4 + 0) * 132 + m] = ast[r].x; sp[(kf * 4 + 1) * 132 + m] = ast[r].y;
            sp[(kf * 4 + 2) * 132 + m] = ast[r].z; sp[(kf * 4 + 3) * 132 + m] = ast[r].w;
        }
#pragma unroll
        for (int r = 0; r < 2; r++) {
            int idx = t + 256 * r, kk = idx >> 4, nf = idx & 15;
            *(float4*)&sB[kk][nf * 4] = bst[r];
        }
        __syncthreads();
        if (ch + 1 < nch) {
            int k0 = (ch + 1) * 32;
#pragma unroll
            for (int r = 0; r < 4; r++) {
                int idx = t + 256 * r, m = idx >> 3, kf = idx & 7;
                ast[r] = *(const float4*)(A + (size_t)(m0 + m) * K + k0 + kf * 4);
            }
#pragma unroll
            for (int r = 0; r < 2; r++) {
                int idx = t + 256 * r, kk = idx >> 4, nf = idx & 15;
                bst[r] = *(const float4*)(B + (size_t)(k0 + kk) * N + n0 + nf * 4);
            }
        }
#pragma unroll 8
        for (int k = 0; k < 32; k++) {
            F4U a0, a1, bv;
            a0.f = *(const float4*)&sA[k][tm * 4];
            a1.f = *(const float4*)&sA[k][tm * 4 + 2];
            bv.f = *(const float4*)&sB[k][tn * 4];
            unsigned long long d0 = dup2(bv.f.x), d1 = dup2(bv.f.y),
                               d2 = dup2(bv.f.z), d3 = dup2(bv.f.w);
            fmax2(acc[0][0], a0.u[0], d0); fmax2(acc[0][1], a0.u[1], d0);
            fmax2(acc[0][2], a1.u[0], d0); fmax2(acc[0][3], a1.u[1], d0);
            fmax2(acc[1][0], a0.u[0], d1); fmax2(acc[1][1], a0.u[1], d1);
            fmax2(acc[1][2], a1.u[0], d1); fmax2(acc[1][3], a1.u[1], d1);
            fmax2(acc[2][0], a0.u[0], d2); fmax2(acc[2][1], a0.u[1], d2);
            fmax2(acc[2][2], a1.u[0], d2); fmax2(acc[2][3], a1.u[1], d2);
            fmax2(acc[3][0], a0.u[0], d3); fmax2(acc[3][1], a0.u[1], d3);
            fmax2(acc[3][2], a1.u[0], d3); fmax2(acc[3][3], a1.u[1], d3);
        }
        __syncthreads();
    }
#pragma unroll
    for (int ni = 0; ni < 4; ni++) {
        int n = n0 + tn * 4 + ni;
        float bv = bias ? bias[n] : 0.f;
#pragma unroll
        for (int p = 0; p < 4; p++) {
            U2F v; v.u = acc[ni][p];
            int m = m0 + tm * 8 + p * 2;
            C[(size_t)m * N + n] = v.f.x + bv;
            C[(size_t)(m + 1) * N + n] = v.f.y + bv;
        }
    }
}

// SIMT GRU step (step 0 only)
__device__ __forceinline__ void gru_phase(unsigned long long (&acc)[3][4],
                                          const float* __restrict__ src, int Kd,
                                          const float* __restrict__ Wf,
                                          int jb, int b0, int t, int tx, int ty,
                                          float* sW, float2 (*sH)[34]) {
    const float* Wp = Wf + (size_t)jb * Kd * 96;
    int nch = Kd >> 5;
    float4 wst0, wst1, wst2, hst0, hst1;
    {
        const float4* wp4 = (const float4*)Wp;
        wst0 = wp4[t]; wst1 = wp4[t + 256]; wst2 = wp4[t + 512];
        int i0 = t, i1 = t + 256;
        hst0 = *(const float4*)(src + (size_t)(b0 + (i0 >> 3)) * Kd + ((i0 & 7) << 2));
        hst1 = *(const float4*)(src + (size_t)(b0 + (i1 >> 3)) * Kd + ((i1 & 7) << 2));
    }
    for (int ch = 0; ch < nch; ch++) {
        ((float4*)sW)[t] = wst0; ((float4*)sW)[t + 256] = wst1; ((float4*)sW)[t + 512] = wst2;
        float* sp = (float*)&sH[0][0];
        {
            int m = t >> 3, kf = t & 7;
            sp[(kf * 4 + 0) * 68 + m] = hst0.x; sp[(kf * 4 + 1) * 68 + m] = hst0.y;
            sp[(kf * 4 + 2) * 68 + m] = hst0.z; sp[(kf * 4 + 3) * 68 + m] = hst0.w;
            int i1 = t + 256; m = i1 >> 3; kf = i1 & 7;
            sp[(kf * 4 + 0) * 68 + m] = hst1.x; sp[(kf * 4 + 1) * 68 + m] = hst1.y;
            sp[(kf * 4 + 2) * 68 + m] = hst1.z; sp[(kf * 4 + 3) * 68 + m] = hst1.w;
        }
        __syncthreads();
        if (ch + 1 < nch) {
            int k0 = (ch + 1) * 32;
            const float4* wp4 = (const float4*)(Wp + (size_t)k0 * 96);
            wst0 = wp4[t]; wst1 = wp4[t + 256]; wst2 = wp4[t + 512];
            int i0 = t, i1 = t + 256;
            hst0 = *(const float4*)(src + (size_t)(b0 + (i0 >> 3)) * Kd + k0 + ((i0 & 7) << 2));
            hst1 = *(const float4*)(src + (size_t)(b0 + (i1 >> 3)) * Kd + k0 + ((i1 & 7) << 2));
        }
#pragma unroll 8
        for (int k = 0; k < 32; k++) {
            F4U a0, a1;
            a0.f = *(const float4*)&sH[k][ty * 4];
            a1.f = *(const float4*)&sH[k][ty * 4 + 2];
            float w0 = sW[k * 96 + tx], w1 = sW[k * 96 + 32 + tx], w2 = sW[k * 96 + 64 + tx];
            unsigned long long d0 = dup2(w0), d1 = dup2(w1), d2 = dup2(w2);
            fmax2(acc[0][0], a0.u[0], d0); fmax2(acc[0][1], a0.u[1], d0);
            fmax2(acc[0][2], a1.u[0], d0); fmax2(acc[0][3], a1.u[1], d0);
            fmax2(acc[1][0], a0.u[0], d1); fmax2(acc[1][1], a0.u[1], d1);
            fmax2(acc[1][2], a1.u[0], d1); fmax2(acc[1][3], a1.u[1], d1);
            fmax2(acc[2][0], a0.u[0], d2); fmax2(acc[2][1], a0.u[1], d2);
            fmax2(acc[2][2], a1.u[0], d2); fmax2(acc[2][3], a1.u[1], d2);
        }
        __syncthreads();
    }
}

__global__ __launch_bounds__(256) void gru_step(const float* __restrict__ inp, int Ki,
                                                const float* __restrict__ Wi,
                                                const float* __restrict__ bi,
                                                const float* __restrict__ hin,
                                                const float* __restrict__ Wh,
                                                const float* __restrict__ bh,
                                                float* __restrict__ hout) {
    __shared__ float  sW[32 * 96];
    __shared__ float2 sH[32][34];
    int jb = blockIdx.x, b0 = blockIdx.y * 64, t = threadIdx.x;
    int tx = t & 31, ty = t >> 5;
    unsigned long long acci[3][4] = {};
    unsigned long long acch[3][4] = {};
    gru_phase(acci, inp, Ki, Wi, jb, b0, t, tx, ty, sW, sH);
    gru_phase(acch, hin, HID, Wh, jb, b0, t, tx, ty, sW, sH);
    int j = jb * 32 + tx;
    float bir = bi[j], bhr = bh[j];
    float biz = bi[HID + j], bhz = bh[HID + j];
    float bin_ = bi[2 * HID + j], bhn = bh[2 * HID + j];
#pragma unroll
    for (int p = 0; p < 4; p++) {
        U2F ir, iz, in_, hr, hz, hn;
        ir.u = acci[0][p]; iz.u = acci[1][p]; in_.u = acci[2][p];
        hr.u = acch[0][p]; hz.u = acch[1][p]; hn.u = acch[2][p];
        int b = b0 + ty * 8 + p * 2;
        float r0 = sigmf(ir.f.x + bir + hr.f.x + bhr);
        float z0 = sigmf(iz.f.x + biz + hz.f.x + bhz);
        float n0 = tanhf(in_.f.x + bin_ + r0 * (hn.f.x + bhn));
        float hp0 = hin[(size_t)b * HID + j];
        hout[(size_t)b * HID + j] = (1.f - z0) * n0 + z0 * hp0;
        float r1 = sigmf(ir.f.y + bir + hr.f.y + bhr);
        float z1 = sigmf(iz.f.y + biz + hz.f.y + bhz);
        float n1 = tanhf(in_.f.y + bin_ + r1 * (hn.f.y + bhn));
        float hp1 = hin[(size_t)(b + 1) * HID + j];
        hout[(size_t)(b + 1) * HID + j] = (1.f - z1) * n1 + z1 * hp1;
    }
}

// ===========================================================================
// fp16 split + packers
// ===========================================================================
union BPK { unsigned short s[8]; uint4 v; };
__device__ __forceinline__ void split8h(const float* v, uint4& hi, uint4& lo) {
    BPK ph, pl;
#pragma unroll
    for (int i = 0; i < 8; i++) {
        __half a = __float2half(v[i]);
        float r = v[i] - __half2float(a);
        __half b = __float2half(r);
        ph.s[i] = *(unsigned short*)&a;
        pl.s[i] = *(unsigned short*)&b;
    }
    hi = ph.v; lo = pl.v;
}
__device__ __forceinline__ uint4 cvt8h(const float* v) {
    BPK p;
#pragma unroll
    for (int i = 0; i < 8; i++) {
        __half a = __float2half(v[i]);
        p.s[i] = *(unsigned short*)&a;
    }
    return p.v;
}

// Gate-fused W image (single fp16): nt(64) x kc(16): 64 rows x 64 k (8KB blocks)
__global__ __launch_bounds__(256) void pack_wimg(const float* __restrict__ Wc,
                                                 const float* __restrict__ Whh) {
    int nt = blockIdx.x, kc = blockIdx.y, tid = threadIdx.x;
    char* dst = g_Wimg + ((size_t)nt * 16 + kc) * 8192;
    for (int u = tid; u < 512; u += 256) {
        int r = u >> 3, unit = u & 7;
        int jt = r >> 2, c = r & 3;
        int j = nt * 16 + jt;
        float v[8];
        if (c < 2) {
            const float* s1 = Wc  + (size_t)(c * HID + j) * HID + kc * 64 + unit * 8;
            const float* s2 = Whh + (size_t)(c * HID + j) * HID + kc * 64 + unit * 8;
            float4 a0 = *(const float4*)s1, a1 = *(const float4*)(s1 + 4);
            float4 b0 = *(const float4*)s2, b1 = *(const float4*)(s2 + 4);
            v[0] = a0.x + b0.x; v[1] = a0.y + b0.y; v[2] = a0.z + b0.z; v[3] = a0.w + b0.w;
            v[4] = a1.x + b1.x; v[5] = a1.y + b1.y; v[6] = a1.z + b1.z; v[7] = a1.w + b1.w;
        } else {
            const float* s1 = (c == 2 ? Wc : Whh) + (size_t)(2 * HID + j) * HID + kc * 64 + unit * 8;
            *(float4*)&v[0] = *(const float4*)s1;
            *(float4*)&v[4] = *(const float4*)(s1 + 4);
        }
        uint32_t o = sw128((uint32_t)(r * 128 + unit * 16));
        *(uint4*)(dst + o) = cvt8h(v);
    }
}

// W_fc images (fp16 hi/lo): nt(6) x kc(16): 128 rows x 64 k
__global__ __launch_bounds__(256) void pack_wfcimg(const float* __restrict__ Wfc) {
    int nt = blockIdx.x, kc = blockIdx.y, tid = threadIdx.x;
    char* dst = g_Wfcimg + ((size_t)nt * 16 + kc) * 32768;
    for (int u = tid; u < 1024; u += 256) {
        int r = u >> 3, unit = u & 7;
        const float* srcrow = Wfc + (size_t)(nt * 128 + r) * HID + kc * 64 + unit * 8;
        float v[8];
        *(float4*)&v[0] = *(const float4*)srcrow;
        *(float4*)&v[4] = *(const float4*)(srcrow + 4);
        uint4 hi, lo; split8h(v, hi, lo);
        uint32_t o = sw128((uint32_t)(r * 128 + unit * 16));
        *(uint4*)(dst + o) = hi;
        *(uint4*)(dst + 16384 + o) = lo;
    }
}

// h_1 (g_H slot1) -> fp16 A image for t=1
__global__ __launch_bounds__(256) void h2img() {
    int mh = blockIdx.x, kc = blockIdx.y, tid = threadIdx.x;
    char* dst = g_Aimg + ((size_t)(1 * 2 + mh) * 16 + kc) * 16384;
    for (int u = tid; u < 1024; u += 256) {
        int r = u >> 3, unit = u & 7;
        const float* hp = g_H + ((size_t)1 * BATCH + mh * 128 + r) * HID + kc * 64 + unit * 8;
        float v[8];
        *(float4*)&v[0] = *(const float4*)hp;
        *(float4*)&v[4] = *(const float4*)(hp + 4);
        uint32_t o = sw128((uint32_t)(r * 128 + unit * 16));
        *(uint4*)(dst + o) = cvt8h(v);
    }
}

// ===========================================================================
// über-kernel: per-chunk dataflow recurrence (slot = producer kc group)
// ===========================================================================
#define WRES 131072      // resident W: 64 rows x 1024 k fp16
#define RSTG 32768       // A stage: 128 rows x 128 k fp16
#define OSTG 98304       // out stage: A 32K + Bfc(hi/lo) 64K
#define UBER_DYN 229376  // 224 KB

__device__ __forceinline__ float fast_tanh(float x) {
    float e = __expf(-2.f * x);
    return __fdividef(1.f - e, 1.f + e);
}
__device__ __forceinline__ float fast_sig(float x) {
    return __fdividef(1.f, 1.f + __expf(-x));
}

__device__ __forceinline__ void rec_step(uint32_t base, int t, int nt, int mh,
                                         int tid, const float (&rb)[4],
                                         const float (&zb)[4],
                                         const float (&nb)[4],
                                         const float (&nhb)[4],
                                         float (&hcur)[8]) {
    int wid = tid >> 5, lane = tid & 31;
    int wm = wid & 3, wn = wid >> 2;
    const char* Asrc = g_Aimg + (size_t)(t * 2 + mh) * (16 * 16384);
    uint32_t aBase = base + WRES;
    const unsigned* slots = &g_barm8[mh][0];
    unsigned tgt = 8u * (unsigned)(t - 1);   // producers done with step t-1 => image t ready

    float acc[2][4][4];
#pragma unroll
    for (int a = 0; a < 2; a++)
#pragma unroll
        for (int b = 0; b < 4; b++)
#pragma unroll
            for (int cc = 0; cc < 4; cc++) acc[a][b][cc] = 0.f;

    // prologue: gate chunks 0,1 on slots 0,1 (parallel lanes), then issue
    if (tid < 2) {
        while (ld_acquire(&slots[tid * 32]) < tgt) __nanosleep(32);
    }
    __syncthreads();
#pragma unroll
    for (int pc = 0; pc < 2; pc++) {
        uint32_t d = aBase + pc * RSTG;
#pragma unroll
        for (int q = 0; q < 8; q++)
            cpa16(d + q * 4096 + tid * 16, Asrc + (size_t)pc * 32768 + q * 4096 + tid * 16);
        CP_COMMIT();
    }

    for (int c = 0; c < 8; c++) {
        if (c == 7) { CP_WAIT(0); } else { CP_WAIT(1); }
        // gate chunk c+2 before the rendezvous that precedes its issue
        if (c + 2 < 8 && tid == 0) {
            while (ld_acquire(&slots[(c + 2) * 32]) < tgt) __nanosleep(32);
        }
        __syncthreads();
        if (c + 2 < 8) {
            uint32_t d = aBase + ((c + 2) % 3) * RSTG;
#pragma unroll
            for (int q = 0; q < 8; q++)
                cpa16(d + q * 4096 + tid * 16, Asrc + (size_t)(c + 2) * 32768 + q * 4096 + tid * 16);
            CP_COMMIT();
        }
        uint32_t sA = aBase + (c % 3) * RSTG;
        uint32_t sW = base + c * 16384;
#pragma unroll
        for (int kk = 0; kk < 8; kk++) {
            uint32_t ah[2][4], bh[2][4];
            int blk = kk >> 2;
            int seg = (kk & 3) * 32 + (lane >> 4) * 16;
#pragma unroll
            for (int mt = 0; mt < 2; mt++) {
                int r = wm * 32 + mt * 16 + (lane & 15);
                ldsm4(ah[mt], sA + blk * 16384 + sw128((uint32_t)(r * 128 + seg)));
            }
#pragma unroll
            for (int nq = 0; nq < 2; nq++) {
                int r = wn * 32 + nq * 16 + (lane & 15);
                ldsm4(bh[nq], sW + blk * 8192 + sw128((uint32_t)(r * 128 + seg)));
            }
#pragma unroll
            for (int mt = 0; mt < 2; mt++)
#pragma unroll
                for (int n8 = 0; n8 < 4; n8++) {
                    int nq = n8 >> 1, hf = n8 & 1;
                    mma16816h(acc[mt][n8], ah[mt], bh[nq][hf], bh[nq][hf + 2]);
                }
        }
    }

    // ---- shfl-exchange epilogue (arithmetic-identical, R12-proven) ----
    int p = lane & 1;
#pragma unroll
    for (int n8 = 0; n8 < 4; n8++) {
        float s0 = p ? acc[0][n8][0] : acc[1][n8][0];
        float s1 = p ? acc[0][n8][1] : acc[1][n8][1];
        float s2 = p ? acc[0][n8][2] : acc[1][n8][2];
        float s3 = p ? acc[0][n8][3] : acc[1][n8][3];
        float o0 = __shfl_xor_sync(0xffffffffu, s0, 1);
        float o1 = __shfl_xor_sync(0xffffffffu, s1, 1);
        float o2 = __shfl_xor_sync(0xffffffffu, s2, 1);
        float o3 = __shfl_xor_sync(0xffffffffu, s3, 1);
        float rz0 = p ? o0 : acc[0][n8][0];
        float rz1 = p ? o1 : acc[0][n8][1];
        float rz2 = p ? o2 : acc[0][n8][2];
        float rz3 = p ? o3 : acc[0][n8][3];
        float nh0 = p ? acc[1][n8][0] : o0;
        float nh1 = p ? acc[1][n8][1] : o1;
        float nh2 = p ? acc[1][n8][2] : o2;
        float nh3 = p ? acc[1][n8][3] : o3;
        float rg = fast_sig(rz0 + rb[n8]);
        float zg = fast_sig(rz1 + zb[n8]);
        float ng = fast_tanh(nh0 + nb[n8] + rg * (nh1 + nhb[n8]));
        hcur[n8 * 2]     = (1.f - zg) * ng + zg * hcur[n8 * 2];
        rg = fast_sig(rz2 + rb[n8]);
        zg = fast_sig(rz3 + zb[n8]);
        ng = fast_tanh(nh2 + nb[n8] + rg * (nh3 + nhb[n8]));
        hcur[n8 * 2 + 1] = (1.f - zg) * ng + zg * hcur[n8 * 2 + 1];
    }

    // image write: 8 scattered fp16 stores
    {
        int r0 = wm * 32 + p * 16 + (lane >> 2);
        int lu = wn * 8 + ((lane & 3) >> 1);
        char* dst = g_Aimg + ((size_t)((t + 1) * 2 + mh) * 16 + (nt >> 2)) * 16384;
        uint32_t cbase = (uint32_t)((nt & 3) * 32 + lu * 2);
#pragma unroll
        for (int n8 = 0; n8 < 4; n8++) {
            __half h0 = __float2half(hcur[n8 * 2]);
            __half h1 = __float2half(hcur[n8 * 2 + 1]);
            uint32_t off0 = (uint32_t)(r0 * 128) + cbase + (uint32_t)(n8 * 4);
            *(unsigned short*)(dst + sw128(off0)) = *(unsigned short*)&h0;
            *(unsigned short*)(dst + sw128(off0 + 8 * 128)) = *(unsigned short*)&h1;
        }
    }

    // arrive at own slot (kc group = nt>>3); NO global wait — dataflow gates next step
    __syncthreads();
    if (tid == 0) atom_add_release(&g_barm8[mh][(nt >> 3) * 32], 1u);
}

__device__ __forceinline__ void out_tile(uint32_t base, int tt, int ont, int omh,
                                         int tid, float* __restrict__ out,
                                         const float* __restrict__ bfc) {
    int wid = tid >> 5, lane = tid & 31;
    int wm = wid & 1, wn = wid >> 1;
    const char* Asrc = g_Aimg + (size_t)(tt * 2 + omh) * (16 * 16384);
    const char* Bsrc = g_Wfcimg + (size_t)ont * (16 * 32768);

    float acc[4][4][4];
#pragma unroll
    for (int a = 0; a < 4; a++)
#pragma unroll
        for (int b = 0; b < 4; b++)
#pragma unroll
            for (int cc = 0; cc < 4; cc++) acc[a][b][cc] = 0.f;

    {
        uint32_t d = base;
#pragma unroll
        for (int q = 0; q < 8; q++) cpa16(d + q * 4096 + tid * 16, Asrc + q * 4096 + tid * 16);
#pragma unroll
        for (int q = 0; q < 16; q++) cpa16(d + 32768 + q * 4096 + tid * 16, Bsrc + q * 4096 + tid * 16);
        CP_COMMIT();
    }

    for (int c = 0; c < 8; c++) {
        if (c < 7) {
            uint32_t d = base + ((c + 1) & 1) * OSTG;
#pragma unroll
            for (int q = 0; q < 8; q++)
                cpa16(d + q * 4096 + tid * 16, Asrc + (size_t)(c + 1) * 32768 + q * 4096 + tid * 16);
#pragma unroll
            for (int q = 0; q < 16; q++)
                cpa16(d + 32768 + q * 4096 + tid * 16, Bsrc + (size_t)(c + 1) * 65536 + q * 4096 + tid * 16);
            CP_COMMIT();
            CP_WAIT(1);
        } else {
            CP_WAIT(0);
        }
        __syncthreads();
        uint32_t sA = base + (c & 1) * OSTG;
        uint32_t sB = sA + 32768;
#pragma unroll
        for (int kk = 0; kk < 8; kk++) {
            uint32_t ah[4][4], bh[2][4], bl[2][4];
            int blk = kk >> 2;
            int seg = (kk & 3) * 32 + (lane >> 4) * 16;
#pragma unroll
            for (int mt = 0; mt < 4; mt++) {
                int r = wm * 64 + mt * 16 + (lane & 15);
                ldsm4(ah[mt], sA + blk * 16384 + sw128((uint32_t)(r * 128 + seg)));
            }
#pragma unroll
            for (int nq = 0; nq < 2; nq++) {
                int r = wn * 32 + nq * 16 + (lane & 15);
                uint32_t off = blk * 32768 + sw128((uint32_t)(r * 128 + seg));
                ldsm4(bh[nq], sB + off);
                ldsm4(bl[nq], sB + 16384 + off);
            }
#pragma unroll
            for (int mt = 0; mt < 4; mt++)
#pragma unroll
                for (int n8 = 0; n8 < 4; n8++) {
                    int nq = n8 >> 1, hf = n8 & 1;
                    mma16816h(acc[mt][n8], ah[mt], bh[nq][hf], bh[nq][hf + 2]);
                    mma16816h(acc[mt][n8], ah[mt], bl[nq][hf], bl[nq][hf + 2]);
                }
        }
        __syncthreads();
    }

    size_t row0 = (size_t)(tt - 1) * BATCH + omh * 128;
#pragma unroll
    for (int mt = 0; mt < 4; mt++)
#pragma unroll
        for (int n8 = 0; n8 < 4; n8++) {
            int rr = wm * 64 + mt * 16 + (lane >> 2);
            int cc = ont * 128 + wn * 32 + n8 * 8 + 2 * (lane & 3);
            float2 bv = *(const float2*)(bfc + cc);
            float2 v0 = make_float2(acc[mt][n8][0] + bv.x, acc[mt][n8][1] + bv.y);
            float2 v1 = make_float2(acc[mt][n8][2] + bv.x, acc[mt][n8][3] + bv.y);
            *(float2*)(out + (row0 + rr) * OUTD + cc)     = v0;
            *(float2*)(out + (row0 + rr + 8) * OUTD + cc) = v1;
        }
}

__global__ __launch_bounds__(256, 1) void uber(int T, const float* __restrict__ bhh,
                                               float* __restrict__ out,
                                               const float* __restrict__ bfc) {
    extern __shared__ char dsm[];
    __shared__ unsigned s_idx;
    uint32_t base = smem_u32(dsm);
    int bid = blockIdx.x, tid = threadIdx.x;

    if (bid < 128 && T > 1) {
        int nt = bid >> 1, mh = bid & 1;

        // load W resident (128 KB, once)
        {
            const char* Wsrc = g_Wimg + (size_t)nt * (16 * 8192);
#pragma unroll
            for (int q = 0; q < 32; q++)
                cpa16(base + q * 4096 + tid * 16, Wsrc + q * 4096 + tid * 16);
            CP_COMMIT(); CP_WAIT(0);
            __syncthreads();
        }

        // hoist per-thread gate biases + initial h (register-carried, acc-layout)
        float rb[4], zb[4], nb[4], nhb[4], hcur[8];
        {
            int wid = tid >> 5, lane = tid & 31;
            int wm = wid & 3, wn = wid >> 2;
            int p = lane & 1;
            int r0 = wm * 32 + p * 16 + (lane >> 2);
            int lu = wn * 8 + ((lane & 3) >> 1);
            int b0 = mh * 128 + r0;
#pragma unroll
            for (int n8 = 0; n8 < 4; n8++) {
                int j = nt * 16 + lu + n8 * 2;
                rb[n8]  = g_bcomb[j] + bhh[j];
                zb[n8]  = g_bcomb[HID + j] + bhh[HID + j];
                nb[n8]  = g_bcomb[2 * HID + j];
                nhb[n8] = bhh[2 * HID + j];
                hcur[n8 * 2]     = g_H[(size_t)(BATCH + b0) * HID + j];
                hcur[n8 * 2 + 1] = g_H[(size_t)(BATCH + b0 + 8) * HID + j];
            }
        }

        for (int t = 1; t < T; t++)
            rec_step(base, t, nt, mh, tid, rb, zb, nb, nhb, hcur);
    }

    // out-tile work queue (all CTAs eventually)
    unsigned total = 12u * (unsigned)T;
    for (;;) {
        __syncthreads();
        if (tid == 0) s_idx = atomicAdd(&g_outq, 1u);
        __syncthreads();
        unsigned idx = s_idx;
        if (idx >= total) break;
        int tt = (int)(idx / 12u) + 1;
        int rem = (int)(idx % 12u);
        int ont = rem % 6, omh = rem / 6;
        unsigned tgt = 8u * (unsigned)(tt - 1);
        if (tid < 8) {
            while (ld_acquire(&g_barm8[omh][tid * 32]) < tgt) __nanosleep(128);
        }
        __syncthreads();
        out_tile(base, tt, ont, omh, tid, out, bfc);
    }
}

// ===========================================================================
extern "C" void kernel_launch(void* const* d_in, const int* in_sizes, int n_in,
                              void* d_out, int out_size) {
    const float* src    = (const float*)d_in[0];
    const float* hidden = (const float*)d_in[2];
    const float* W_ih   = (const float*)d_in[3];
    const float* W_hh   = (const float*)d_in[4];
    const float* b_ih   = (const float*)d_in[5];
    const float* b_hh   = (const float*)d_in[6];
    const float* W_fc   = (const float*)d_in[7];
    const float* b_fc   = (const float*)d_in[8];
    float* out = (float*)d_out;

    int T = out_size / (BATCH * OUTD);
    if (T > TMAX) T = TMAX;
    if (T < 1) T = 1;

    float *pH, *pWihf, *pWhhf, *pWc, *pbc;
    cudaGetSymbolAddress((void**)&pH, g_H);
    cudaGetSymbolAddress((void**)&pWihf, g_Wih_f);
    cudaGetSymbolAddress((void**)&pWhhf, g_Whh_f);
    cudaGetSymbolAddress((void**)&pWc, g_Wc);
    cudaGetSymbolAddress((void**)&pbc, g_bcomb);

    cudaFuncSetAttribute(uber, cudaFuncAttributeMaxDynamicSharedMemorySize, UBER_DYN);

    // --- precompute ---
    init_sync<<<1, 1>>>();
    pack_w<<<dim3(OUTD / 32, NJB, 3), 256>>>(pWihf, W_ih, OUTD);
    pack_w<<<dim3(HID / 32, NJB, 3), 256>>>(pWhhf, W_hh, HID);
    gemm_nn<<<dim3(HID / 64, (3 * HID) / 128), 256>>>(W_ih, W_fc, nullptr, pWc,
                                                      3 * HID, HID, OUTD);
    bcomb_k<<<(3 * HID) / 8, 256>>>(W_ih, b_fc, b_ih, pbc);
    copy_f<<<(BATCH * HID / 4 + 255) / 256, 256>>>(pH, hidden, BATCH * HID / 4);
    pack_wimg<<<dim3(64, 16), 256>>>(pWc, W_hh);
    pack_wfcimg<<<dim3(6, 16), 256>>>(W_fc);

    // --- step 0 (SIMT fp32, K=768 input path): h_0 (slot0) -> h_1 (slot1) ---
    gru_step<<<dim3(NJB, BATCH / 64), 256>>>(src, OUTD, pWihf, b_ih,
                                             pH, pWhhf, b_hh,
                                             pH + (size_t)BATCH * HID);
    h2img<<<dim3(2, 16), 256>>>();

    // --- über-kernel (per-chunk dataflow) ---
    uber<<<148, 256, UBER_DYN>>>(T, b_hh, out, b_fc);
}

// round 14
// speedup vs baseline: 1.1772x; 1.1772x over previous
#include <cuda_runtime.h>
#include <cuda_fp16.h>
#include <math.h>
#include <stdint.h>

#define HID   1024
#define OUTD  768
#define BATCH 256
#define TMAX  256

// ===========================================================================
// helpers
// ===========================================================================
__device__ __forceinline__ uint32_t smem_u32(const void* p) {
    uint32_t a;
    asm("{ .reg .u64 t; cvta.to.shared.u64 t, %1; cvt.u32.u64 %0, t; }" : "=r"(a) : "l"(p));
    return a;
}
__device__ __host__ __forceinline__ uint32_t sw128(uint32_t off) {
    return off ^ ((off >> 3) & 0x70);
}
__device__ __forceinline__ void cpa16(uint32_t dst, const void* src) {
    asm volatile("cp.async.cg.shared.global [%0], [%1], 16;" :: "r"(dst), "l"(src));
}
#define CP_COMMIT() asm volatile("cp.async.commit_group;" ::: "memory")
#define CP_WAIT(n)  asm volatile("cp.async.wait_group %0;" :: "n"(n) : "memory")

__device__ __forceinline__ void ldsm4(uint32_t (&r)[4], uint32_t addr) {
    asm volatile("ldmatrix.sync.aligned.m8n8.x4.shared.b16 {%0,%1,%2,%3}, [%4];"
        : "=r"(r[0]), "=r"(r[1]), "=r"(r[2]), "=r"(r[3]) : "r"(addr));
}
__device__ __forceinline__ void mma16816h(float (&d)[4], const uint32_t (&a)[4],
                                          uint32_t b0, uint32_t b1) {
    asm volatile("mma.sync.aligned.m16n8k16.row.col.f32.f16.f16.f32 "
        "{%0,%1,%2,%3}, {%4,%5,%6,%7}, {%8,%9}, {%0,%1,%2,%3};"
        : "+f"(d[0]), "+f"(d[1]), "+f"(d[2]), "+f"(d[3])
        : "r"(a[0]), "r"(a[1]), "r"(a[2]), "r"(a[3]), "r"(b0), "r"(b1));
}

__device__ __forceinline__ unsigned atom_add_release(unsigned* p, unsigned v) {
    unsigned old;
    asm volatile("atom.release.gpu.global.add.u32 %0, [%1], %2;"
        : "=r"(old) : "l"(p), "r"(v) : "memory");
    return old;
}
__device__ __forceinline__ unsigned ld_acquire(const unsigned* p) {
    unsigned v;
    asm volatile("ld.acquire.gpu.global.u32 %0, [%1];" : "=r"(v) : "l"(p) : "memory");
    return v;
}

// ===========================================================================
// device scratch
// ===========================================================================
__device__ float g_Wc[3 * HID * HID];               // fp32 W_comb
__device__ float g_bcomb[3 * HID];
__device__ unsigned g_barm8[2][8 * 32];             // per-mh, 8 split arrival counters
__device__ unsigned g_outq;
// fp16 SW128 images (all blocks: rows x 64k, 128B rows)
__device__ __align__(1024) char g_Aimg[(size_t)(TMAX + 1) * 2 * 16 * 16384]; // [t][mh][kc16] 128x64
__device__ __align__(1024) char g_Wimg[(size_t)64 * 16 * 8192];              // rec W single fp16 [nt][kc16] 64x64
__device__ __align__(1024) char g_Wfcimg[(size_t)6 * 16 * 32768];            // out W hi/lo [nt][kc16] 128x64
__device__ __align__(1024) char g_WihImg[(size_t)24 * 12 * 32768];           // W_ih hi/lo [mt][kb12] 128x64
__device__ __align__(1024) char g_WfcTImg[(size_t)8 * 12 * 32768];           // W_fc^T hi/lo [nt][kb12] 128x64
__device__ __align__(1024) char g_W0img[(size_t)64 * 28 * 8192];             // step0 W single fp16 [nt][kb28] 64x64
__device__ __align__(1024) char g_A0img[(size_t)2 * 28 * 16384];             // step0 A [mh][kb28] 128x64

// ===========================================================================
// fp16 split + packers
// ===========================================================================
union BPK { unsigned short s[8]; uint4 v; };
__device__ __forceinline__ void split8h(const float* v, uint4& hi, uint4& lo) {
    BPK ph, pl;
#pragma unroll
    for (int i = 0; i < 8; i++) {
        __half a = __float2half(v[i]);
        float r = v[i] - __half2float(a);
        __half b = __float2half(r);
        ph.s[i] = *(unsigned short*)&a;
        pl.s[i] = *(unsigned short*)&b;
    }
    hi = ph.v; lo = pl.v;
}
__device__ __forceinline__ uint4 cvt8h(const float* v) {
    BPK p;
#pragma unroll
    for (int i = 0; i < 8; i++) {
        __half a = __float2half(v[i]);
        p.s[i] = *(unsigned short*)&a;
    }
    return p.v;
}

__global__ __launch_bounds__(256) void bcomb_k(const float* __restrict__ Wih,
                                               const float* __restrict__ bfc,
                                               const float* __restrict__ bih,
                                               float* __restrict__ out) {
    int j = blockIdx.x * 8 + (threadIdx.x >> 5);
    int lane = threadIdx.x & 31;
    float s = 0.f;
    for (int o = lane; o < OUTD; o += 32) s += Wih[(size_t)j * OUTD + o] * bfc[o];
#pragma unroll
    for (int off = 16; off; off >>= 1) s += __shfl_xor_sync(0xffffffffu, s, off);
    if (lane == 0) out[j] = s + bih[j];
}

__global__ void init_sync() {
    for (int m = 0; m < 2; m++)
        for (int s = 0; s < 8; s++) g_barm8[m][s * 32] = 0;
    g_outq = 0;
}

// W_ih [3072 x 768] -> hi/lo blocks [mt 24][kb 12]
__global__ __launch_bounds__(256) void pack_wih_img(const float* __restrict__ Wih) {
    int mt = blockIdx.x, kb = blockIdx.y, tid = threadIdx.x;
    char* dst = g_WihImg + ((size_t)mt * 12 + kb) * 32768;
    for (int u = tid; u < 1024; u += 256) {
        int r = u >> 3, unit = u & 7;
        const float* s = Wih + (size_t)(mt * 128 + r) * OUTD + kb * 64 + unit * 8;
        float v[8];
        *(float4*)&v[0] = *(const float4*)s;
        *(float4*)&v[4] = *(const float4*)(s + 4);
        uint4 hi, lo; split8h(v, hi, lo);
        uint32_t o = sw128((uint32_t)(r * 128 + unit * 16));
        *(uint4*)(dst + o) = hi;
        *(uint4*)(dst + 16384 + o) = lo;
    }
}

// W_fc^T: B[n][k] = W_fc[k][n]  -> hi/lo blocks [nt 8][kb 12]
__global__ __launch_bounds__(256) void pack_wfcT_img(const float* __restrict__ Wfc) {
    int nt = blockIdx.x, kb = blockIdx.y, tid = threadIdx.x;
    char* dst = g_WfcTImg + ((size_t)nt * 12 + kb) * 32768;
    for (int u = tid; u < 1024; u += 256) {
        int r = u >> 3, unit = u & 7;
        int n = nt * 128 + r;
        int k0 = kb * 64 + unit * 8;
        float v[8];
#pragma unroll
        for (int i = 0; i < 8; i++) v[i] = Wfc[(size_t)(k0 + i) * HID + n];
        uint4 hi, lo; split8h(v, hi, lo);
        uint32_t o = sw128((uint32_t)(r * 128 + unit * 16));
        *(uint4*)(dst + o) = hi;
        *(uint4*)(dst + 16384 + o) = lo;
    }
}

// HMMA W_comb: g_Wc[3072][1024] = W_ih @ W_fc  (3-product hi/lo)
#define WCG_STG 65536
__global__ __launch_bounds__(256, 1) void wcomb_gemm() {
    extern __shared__ char dsm[];
    uint32_t base = smem_u32(dsm);
    int tid = threadIdx.x, wid = tid >> 5, lane = tid & 31;
    int nt = blockIdx.x, mt = blockIdx.y;
    int wm = wid & 1, wn = wid >> 1;
    const char* Asrc = g_WihImg + (size_t)mt * (12 * 32768);
    const char* Bsrc = g_WfcTImg + (size_t)nt * (12 * 32768);

    float acc[4][4][4];
#pragma unroll
    for (int a = 0; a < 4; a++)
#pragma unroll
        for (int b = 0; b < 4; b++)
#pragma unroll
            for (int c = 0; c < 4; c++) acc[a][b][c] = 0.f;

    {
#pragma unroll
        for (int q = 0; q < 8; q++) {
            cpa16(base + q * 4096 + tid * 16, Asrc + q * 4096 + tid * 16);
            cpa16(base + 32768 + q * 4096 + tid * 16, Bsrc + q * 4096 + tid * 16);
        }
        CP_COMMIT();
    }
    for (int c = 0; c < 12; c++) {
        if (c < 11) {
            uint32_t d = base + ((c + 1) & 1) * WCG_STG;
#pragma unroll
            for (int q = 0; q < 8; q++) {
                cpa16(d + q * 4096 + tid * 16, Asrc + (size_t)(c + 1) * 32768 + q * 4096 + tid * 16);
                cpa16(d + 32768 + q * 4096 + tid * 16, Bsrc + (size_t)(c + 1) * 32768 + q * 4096 + tid * 16);
            }
            CP_COMMIT();
            CP_WAIT(1);
        } else {
            CP_WAIT(0);
        }
        __syncthreads();
        uint32_t sA = base + (c & 1) * WCG_STG;
        uint32_t sB = sA + 32768;
#pragma unroll
        for (int kk = 0; kk < 4; kk++) {
            uint32_t ah[4][4], al[4][4], bh[2][4], bl[2][4];
            int seg = kk * 32 + (lane >> 4) * 16;
#pragma unroll
            for (int m4 = 0; m4 < 4; m4++) {
                int r = wm * 64 + m4 * 16 + (lane & 15);
                uint32_t off = sw128((uint32_t)(r * 128 + seg));
                ldsm4(ah[m4], sA + off);
                ldsm4(al[m4], sA + 16384 + off);
            }
#pragma unroll
            for (int nq = 0; nq < 2; nq++) {
                int r = wn * 32 + nq * 16 + (lane & 15);
                uint32_t off = sw128((uint32_t)(r * 128 + seg));
                ldsm4(bh[nq], sB + off);
                ldsm4(bl[nq], sB + 16384 + off);
            }
#pragma unroll
            for (int m4 = 0; m4 < 4; m4++)
#pragma unroll
                for (int n8 = 0; n8 < 4; n8++) {
                    int nq = n8 >> 1, hf = n8 & 1;
                    mma16816h(acc[m4][n8], ah[m4], bh[nq][hf], bh[nq][hf + 2]);
                    mma16816h(acc[m4][n8], ah[m4], bl[nq][hf], bl[nq][hf + 2]);
                    mma16816h(acc[m4][n8], al[m4], bh[nq][hf], bh[nq][hf + 2]);
                }
        }
        __syncthreads();
    }
#pragma unroll
    for (int m4 = 0; m4 < 4; m4++)
#pragma unroll
        for (int n8 = 0; n8 < 4; n8++) {
            int m = mt * 128 + wm * 64 + m4 * 16 + (lane >> 2);
            int n = nt * 128 + wn * 32 + n8 * 8 + 2 * (lane & 3);
            *(float2*)&g_Wc[(size_t)m * HID + n]       = make_float2(acc[m4][n8][0], acc[m4][n8][1]);
            *(float2*)&g_Wc[(size_t)(m + 8) * HID + n] = make_float2(acc[m4][n8][2], acc[m4][n8][3]);
        }
}

// Gate-fused rec W image (single fp16): [nt 64][kc 16] 64 rows x 64 k
// row = jt*4 + c;  c=0: Wc_r+Whh_r, c=1: Wc_z+Whh_z, c=2: Wc_n, c=3: Whh_n
__global__ __launch_bounds__(256) void pack_wimg(const float* __restrict__ Whh) {
    int nt = blockIdx.x, kc = blockIdx.y, tid = threadIdx.x;
    char* dst = g_Wimg + ((size_t)nt * 16 + kc) * 8192;
    for (int u = tid; u < 512; u += 256) {
        int r = u >> 3, unit = u & 7;
        int jt = r >> 2, c = r & 3;
        int j = nt * 16 + jt;
        float v[8];
        if (c < 2) {
            const float* s1 = g_Wc + (size_t)(c * HID + j) * HID + kc * 64 + unit * 8;
            const float* s2 = Whh  + (size_t)(c * HID + j) * HID + kc * 64 + unit * 8;
            float4 a0 = *(const float4*)s1, a1 = *(const float4*)(s1 + 4);
            float4 b0 = *(const float4*)s2, b1 = *(const float4*)(s2 + 4);
            v[0] = a0.x + b0.x; v[1] = a0.y + b0.y; v[2] = a0.z + b0.z; v[3] = a0.w + b0.w;
            v[4] = a1.x + b1.x; v[5] = a1.y + b1.y; v[6] = a1.z + b1.z; v[7] = a1.w + b1.w;
        } else {
            const float* s1 = (c == 2 ? g_Wc : Whh) + (size_t)(2 * HID + j) * HID + kc * 64 + unit * 8;
            *(float4*)&v[0] = *(const float4*)s1;
            *(float4*)&v[4] = *(const float4*)(s1 + 4);
        }
        uint32_t o = sw128((uint32_t)(r * 128 + unit * 16));
        *(uint4*)(dst + o) = cvt8h(v);
    }
}

// Step0 W image (single fp16, concat K=1792, zero-padded n-gate cols): [nt 64][kb 28]
__global__ __launch_bounds__(256) void pack_w0img(const float* __restrict__ Wih,
                                                  const float* __restrict__ Whh) {
    int nt = blockIdx.x, kb = blockIdx.y, tid = threadIdx.x;
    char* dst = g_W0img + ((size_t)nt * 28 + kb) * 8192;
    for (int u = tid; u < 512; u += 256) {
        int r = u >> 3, unit = u & 7;
        int jt = r >> 2, c = r & 3;
        int j = nt * 16 + jt;
        float v[8] = {0, 0, 0, 0, 0, 0, 0, 0};
        if (kb < 12) {                 // x-part (K 0..767) from W_ih
            int k0 = kb * 64 + unit * 8;
            if (c < 3) {               // c=0:r, c=1:z, c=2:i_n ; c=3 stays 0
                const float* s = Wih + (size_t)(c * HID + j) * OUTD + k0;
                *(float4*)&v[0] = *(const float4*)s;
                *(float4*)&v[4] = *(const float4*)(s + 4);
            }
        } else {                       // h-part (K 768..1791) from W_hh
            int k0 = kb * 64 - 768 + unit * 8;
            if (c != 2) {              // c=0:r, c=1:z, c=3:h_n ; c=2 stays 0
                int g = (c == 3) ? 2 : c;
                const float* s = Whh + (size_t)(g * HID + j) * HID + k0;
                *(float4*)&v[0] = *(const float4*)s;
                *(float4*)&v[4] = *(const float4*)(s + 4);
            }
        }
        uint32_t o = sw128((uint32_t)(r * 128 + unit * 16));
        *(uint4*)(dst + o) = cvt8h(v);
    }
}

// Step0 A image: concat [x0 | h0] fp16: [mh 2][kb 28]
__global__ __launch_bounds__(256) void pack_a0img(const float* __restrict__ src,
                                                  const float* __restrict__ hidden) {
    int mh = blockIdx.x, kb = blockIdx.y, tid = threadIdx.x;
    char* dst = g_A0img + ((size_t)mh * 28 + kb) * 16384;
    for (int u = tid; u < 1024; u += 256) {
        int r = u >> 3, unit = u & 7;
        int b = mh * 128 + r;
        float v[8];
        if (kb < 12) {
            const float* s = src + (size_t)b * OUTD + kb * 64 + unit * 8;
            *(float4*)&v[0] = *(const float4*)s;
            *(float4*)&v[4] = *(const float4*)(s + 4);
        } else {
            const float* s = hidden + (size_t)b * HID + kb * 64 - 768 + unit * 8;
            *(float4*)&v[0] = *(const float4*)s;
            *(float4*)&v[4] = *(const float4*)(s + 4);
        }
        uint32_t o = sw128((uint32_t)(r * 128 + unit * 16));
        *(uint4*)(dst + o) = cvt8h(v);
    }
}

// Out-projection W_fc images (fp16 hi/lo): [nt 6][kc 16] 128 rows x 64 k
__global__ __launch_bounds__(256) void pack_wfcimg(const float* __restrict__ Wfc) {
    int nt = blockIdx.x, kc = blockIdx.y, tid = threadIdx.x;
    char* dst = g_Wfcimg + ((size_t)nt * 16 + kc) * 32768;
    for (int u = tid; u < 1024; u += 256) {
        int r = u >> 3, unit = u & 7;
        const float* srcrow = Wfc + (size_t)(nt * 128 + r) * HID + kc * 64 + unit * 8;
        float v[8];
        *(float4*)&v[0] = *(const float4*)srcrow;
        *(float4*)&v[4] = *(const float4*)(srcrow + 4);
        uint4 hi, lo; split8h(v, hi, lo);
        uint32_t o = sw128((uint32_t)(r * 128 + unit * 16));
        *(uint4*)(dst + o) = hi;
        *(uint4*)(dst + 16384 + o) = lo;
    }
}

// ===========================================================================
// über-kernel
// ===========================================================================
#define WRES 131072
#define RSTG 32768
#define OSTG 98304
#define UBER_DYN 229376

__device__ __forceinline__ float fast_tanh(float x) {
    float e = __expf(-2.f * x);
    return __fdividef(1.f - e, 1.f + e);
}
__device__ __forceinline__ float fast_sig(float x) {
    return __fdividef(1.f, 1.f + __expf(-x));
}

// shared epilogue: gates + image write + barrier (arrive, optional wait)
__device__ __forceinline__ void gru_epilogue(float (&acc)[2][4][4], float (&hcur)[8],
                                             const float (&rb)[4], const float (&zb)[4],
                                             const float (&nb)[4], const float (&nhb)[4],
                                             int s, int nt, int mh, int tid, bool waitNext) {
    int wid = tid >> 5, lane = tid & 31;
    int wm = wid & 3, wn = wid >> 2;
    int p = lane & 1;
#pragma unroll
    for (int n8 = 0; n8 < 4; n8++) {
        float s0 = p ? acc[0][n8][0] : acc[1][n8][0];
        float s1 = p ? acc[0][n8][1] : acc[1][n8][1];
        float s2 = p ? acc[0][n8][2] : acc[1][n8][2];
        float s3 = p ? acc[0][n8][3] : acc[1][n8][3];
        float o0 = __shfl_xor_sync(0xffffffffu, s0, 1);
        float o1 = __shfl_xor_sync(0xffffffffu, s1, 1);
        float o2 = __shfl_xor_sync(0xffffffffu, s2, 1);
        float o3 = __shfl_xor_sync(0xffffffffu, s3, 1);
        float rz0 = p ? o0 : acc[0][n8][0];
        float rz1 = p ? o1 : acc[0][n8][1];
        float rz2 = p ? o2 : acc[0][n8][2];
        float rz3 = p ? o3 : acc[0][n8][3];
        float nh0 = p ? acc[1][n8][0] : o0;
        float nh1 = p ? acc[1][n8][1] : o1;
        float nh2 = p ? acc[1][n8][2] : o2;
        float nh3 = p ? acc[1][n8][3] : o3;
        float rg = fast_sig(rz0 + rb[n8]);
        float zg = fast_sig(rz1 + zb[n8]);
        float ng = fast_tanh(nh0 + nb[n8] + rg * (nh1 + nhb[n8]));
        hcur[n8 * 2]     = (1.f - zg) * ng + zg * hcur[n8 * 2];
        rg = fast_sig(rz2 + rb[n8]);
        zg = fast_sig(rz3 + zb[n8]);
        ng = fast_tanh(nh2 + nb[n8] + rg * (nh3 + nhb[n8]));
        hcur[n8 * 2 + 1] = (1.f - zg) * ng + zg * hcur[n8 * 2 + 1];
    }
    {
        int r0 = wm * 32 + p * 16 + (lane >> 2);
        int lu = wn * 8 + ((lane & 3) >> 1);
        char* dst = g_Aimg + ((size_t)((s + 1) * 2 + mh) * 16 + (nt >> 2)) * 16384;
        uint32_t cbase = (uint32_t)((nt & 3) * 32 + lu * 2);
#pragma unroll
        for (int n8 = 0; n8 < 4; n8++) {
            __half h0 = __float2half(hcur[n8 * 2]);
            __half h1 = __float2half(hcur[n8 * 2 + 1]);
            uint32_t off0 = (uint32_t)(r0 * 128) + cbase + (uint32_t)(n8 * 4);
            *(unsigned short*)(dst + sw128(off0)) = *(unsigned short*)&h0;
            *(unsigned short*)(dst + sw128(off0 + 8 * 128)) = *(unsigned short*)&h1;
        }
    }
    __syncthreads();
    if (tid == 0) atom_add_release(&g_barm8[mh][(nt & 7) * 32], 1u);
    if (waitNext && tid < 8) {
        unsigned tgt = 8u * (unsigned)(s + 1);
        while (ld_acquire(&g_barm8[mh][tid * 32]) < tgt) __nanosleep(32);
    }
    __syncthreads();
}

// steady-state step: resident W, A image s -> image s+1
__device__ __forceinline__ void rec_step(uint32_t base, int s, int nt, int mh,
                                         int tid, const float (&rb)[4],
                                         const float (&zb)[4],
                                         const float (&nb)[4],
                                         const float (&nhb)[4],
                                         float (&hcur)[8], bool waitNext) {
    int wid = tid >> 5, lane = tid & 31;
    int wm = wid & 3, wn = wid >> 2;
    const char* Asrc = g_Aimg + (size_t)(s * 2 + mh) * (16 * 16384);
    uint32_t aBase = base + WRES;

    float acc[2][4][4];
#pragma unroll
    for (int a = 0; a < 2; a++)
#pragma unroll
        for (int b = 0; b < 4; b++)
#pragma unroll
            for (int cc = 0; cc < 4; cc++) acc[a][b][cc] = 0.f;

#pragma unroll
    for (int pc = 0; pc < 2; pc++) {
        uint32_t d = aBase + pc * RSTG;
#pragma unroll
        for (int q = 0; q < 8; q++)
            cpa16(d + q * 4096 + tid * 16, Asrc + (size_t)pc * 32768 + q * 4096 + tid * 16);
        CP_COMMIT();
    }

    for (int c = 0; c < 8; c++) {
        if (c == 7) { CP_WAIT(0); } else { CP_WAIT(1); }
        __syncthreads();
        if (c + 2 < 8) {
            uint32_t d = aBase + ((c + 2) % 3) * RSTG;
#pragma unroll
            for (int q = 0; q < 8; q++)
                cpa16(d + q * 4096 + tid * 16, Asrc + (size_t)(c + 2) * 32768 + q * 4096 + tid * 16);
            CP_COMMIT();
        }
        uint32_t sA = aBase + (c % 3) * RSTG;
        uint32_t sW = base + c * 16384;
#pragma unroll
        for (int kk = 0; kk < 8; kk++) {
            uint32_t ah[2][4], bh[2][4];
            int blk = kk >> 2;
            int seg = (kk & 3) * 32 + (lane >> 4) * 16;
#pragma unroll
            for (int mt = 0; mt < 2; mt++) {
                int r = wm * 32 + mt * 16 + (lane & 15);
                ldsm4(ah[mt], sA + blk * 16384 + sw128((uint32_t)(r * 128 + seg)));
            }
#pragma unroll
            for (int nq = 0; nq < 2; nq++) {
                int r = wn * 32 + nq * 16 + (lane & 15);
                ldsm4(bh[nq], sW + blk * 8192 + sw128((uint32_t)(r * 128 + seg)));
            }
#pragma unroll
            for (int mt = 0; mt < 2; mt++)
#pragma unroll
                for (int n8 = 0; n8 < 4; n8++) {
                    int nq = n8 >> 1, hf = n8 & 1;
                    mma16816h(acc[mt][n8], ah[mt], bh[nq][hf], bh[nq][hf + 2]);
                }
        }
    }
    gru_epilogue(acc, hcur, rb, zb, nb, nhb, s, nt, mh, tid, waitNext);
}

// step 0: streamed W0 (K=1792 concat [x0|h0]), writes image 1
__device__ __forceinline__ void rec_step0(uint32_t base, int nt, int mh, int tid,
                                          const float (&rb)[4], const float (&zb)[4],
                                          const float (&nb)[4], const float (&nhb)[4],
                                          float (&hcur)[8], bool waitNext) {
    int wid = tid >> 5, lane = tid & 31;
    int wm = wid & 3, wn = wid >> 2;
    const char* Asrc = g_A0img + (size_t)mh * (28 * 16384);
    const char* Wsrc = g_W0img + (size_t)nt * (28 * 8192);
    uint32_t aBase = base + WRES;

    float acc[2][4][4];
#pragma unroll
    for (int a = 0; a < 2; a++)
#pragma unroll
        for (int b = 0; b < 4; b++)
#pragma unroll
            for (int cc = 0; cc < 4; cc++) acc[a][b][cc] = 0.f;

#pragma unroll
    for (int pc = 0; pc < 2; pc++) {
        uint32_t dA = aBase + pc * RSTG;
        uint32_t dW = base + pc * 16384;
#pragma unroll
        for (int q = 0; q < 8; q++)
            cpa16(dA + q * 4096 + tid * 16, Asrc + (size_t)pc * 32768 + q * 4096 + tid * 16);
#pragma unroll
        for (int q = 0; q < 4; q++)
            cpa16(dW + q * 4096 + tid * 16, Wsrc + (size_t)pc * 16384 + q * 4096 + tid * 16);
        CP_COMMIT();
    }

    for (int c = 0; c < 14; c++) {
        if (c == 13) { CP_WAIT(0); } else { CP_WAIT(1); }
        __syncthreads();
        if (c + 2 < 14) {
            uint32_t dA = aBase + ((c + 2) % 3) * RSTG;
            uint32_t dW = base + ((c + 2) % 3) * 16384;
#pragma unroll
            for (int q = 0; q < 8; q++)
                cpa16(dA + q * 4096 + tid * 16, Asrc + (size_t)(c + 2) * 32768 + q * 4096 + tid * 16);
#pragma unroll
            for (int q = 0; q < 4; q++)
                cpa16(dW + q * 4096 + tid * 16, Wsrc + (size_t)(c + 2) * 16384 + q * 4096 + tid * 16);
            CP_COMMIT();
        }
        uint32_t sA = aBase + (c % 3) * RSTG;
        uint32_t sW = base + (c % 3) * 16384;
#pragma unroll
        for (int kk = 0; kk < 8; kk++) {
            uint32_t ah[2][4], bh[2][4];
            int blk = kk >> 2;
            int seg = (kk & 3) * 32 + (lane >> 4) * 16;
#pragma unroll
            for (int mt = 0; mt < 2; mt++) {
                int r = wm * 32 + mt * 16 + (lane & 15);
                ldsm4(ah[mt], sA + blk * 16384 + sw128((uint32_t)(r * 128 + seg)));
            }
#pragma unroll
            for (int nq = 0; nq < 2; nq++) {
                int r = wn * 32 + nq * 16 + (lane & 15);
                ldsm4(bh[nq], sW + blk * 8192 + sw128((uint32_t)(r * 128 + seg)));
            }
#pragma unroll
            for (int mt = 0; mt < 2; mt++)
#pragma unroll
                for (int n8 = 0; n8 < 4; n8++) {
                    int nq = n8 >> 1, hf = n8 & 1;
                    mma16816h(acc[mt][n8], ah[mt], bh[nq][hf], bh[nq][hf + 2]);
                }
        }
    }
    gru_epilogue(acc, hcur, rb, zb, nb, nhb, 0, nt, mh, tid, waitNext);
}

__device__ __forceinline__ void out_tile(uint32_t base, int tt, int ont, int omh,
                                         int tid, float* __restrict__ out,
                                         const float* __restrict__ bfc) {
    int wid = tid >> 5, lane = tid & 31;
    int wm = wid & 1, wn = wid >> 1;
    const char* Asrc = g_Aimg + (size_t)(tt * 2 + omh) * (16 * 16384);
    const char* Bsrc = g_Wfcimg + (size_t)ont * (16 * 32768);

    float acc[4][4][4];
#pragma unroll
    for (int a = 0; a < 4; a++)
#pragma unroll
        for (int b = 0; b < 4; b++)
#pragma unroll
            for (int cc = 0; cc < 4; cc++) acc[a][b][cc] = 0.f;

    {
#pragma unroll
        for (int q = 0; q < 8; q++) cpa16(base + q * 4096 + tid * 16, Asrc + q * 4096 + tid * 16);
#pragma unroll
        for (int q = 0; q < 16; q++) cpa16(base + 32768 + q * 4096 + tid * 16, Bsrc + q * 4096 + tid * 16);
        CP_COMMIT();
    }

    for (int c = 0; c < 8; c++) {
        if (c < 7) {
            uint32_t d = base + ((c + 1) & 1) * OSTG;
#pragma unroll
            for (int q = 0; q < 8; q++)
                cpa16(d + q * 4096 + tid * 16, Asrc + (size_t)(c + 1) * 32768 + q * 4096 + tid * 16);
#pragma unroll
            for (int q = 0; q < 16; q++)
                cpa16(d + 32768 + q * 4096 + tid * 16, Bsrc + (size_t)(c + 1) * 65536 + q * 4096 + tid * 16);
            CP_COMMIT();
            CP_WAIT(1);
        } else {
            CP_WAIT(0);
        }
        __syncthreads();
        uint32_t sA = base + (c & 1) * OSTG;
        uint32_t sB = sA + 32768;
#pragma unroll
        for (int kk = 0; kk < 8; kk++) {
            uint32_t ah[4][4], bh[2][4], bl[2][4];
            int blk = kk >> 2;
            int seg = (kk & 3) * 32 + (lane >> 4) * 16;
#pragma unroll
            for (int mt = 0; mt < 4; mt++) {
                int r = wm * 64 + mt * 16 + (lane & 15);
                ldsm4(ah[mt], sA + blk * 16384 + sw128((uint32_t)(r * 128 + seg)));
            }
#pragma unroll
            for (int nq = 0; nq < 2; nq++) {
                int r = wn * 32 + nq * 16 + (lane & 15);
                uint32_t off = blk * 32768 + sw128((uint32_t)(r * 128 + seg));
                ldsm4(bh[nq], sB + off);
                ldsm4(bl[nq], sB + 16384 + off);
            }
#pragma unroll
            for (int mt = 0; mt < 4; mt++)
#pragma unroll
                for (int n8 = 0; n8 < 4; n8++) {
                    int nq = n8 >> 1, hf = n8 & 1;
                    mma16816h(acc[mt][n8], ah[mt], bh[nq][hf], bh[nq][hf + 2]);
                    mma16816h(acc[mt][n8], ah[mt], bl[nq][hf], bl[nq][hf + 2]);
                }
        }
        __syncthreads();
    }

    size_t row0 = (size_t)(tt - 1) * BATCH + omh * 128;
#pragma unroll
    for (int mt = 0; mt < 4; mt++)
#pragma unroll
        for (int n8 = 0; n8 < 4; n8++) {
            int rr = wm * 64 + mt * 16 + (lane >> 2);
            int cc = ont * 128 + wn * 32 + n8 * 8 + 2 * (lane & 3);
            float2 bv = *(const float2*)(bfc + cc);
            float2 v0 = make_float2(acc[mt][n8][0] + bv.x, acc[mt][n8][1] + bv.y);
            float2 v1 = make_float2(acc[mt][n8][2] + bv.x, acc[mt][n8][3] + bv.y);
            *(float2*)(out + (row0 + rr) * OUTD + cc)     = v0;
            *(float2*)(out + (row0 + rr + 8) * OUTD + cc) = v1;
        }
}

__global__ __launch_bounds__(256, 1) void uber(int T, const float* __restrict__ bih,
                                               const float* __restrict__ bhh,
                                               const float* __restrict__ hidden,
                                               float* __restrict__ out,
                                               const float* __restrict__ bfc) {
    extern __shared__ char dsm[];
    __shared__ unsigned s_idx;
    uint32_t base = smem_u32(dsm);
    int bid = blockIdx.x, tid = threadIdx.x;

    if (bid < 128) {
        int nt = bid >> 1, mh = bid & 1;
        int wid = tid >> 5, lane = tid & 31;
        int wm = wid & 3, wn = wid >> 2;
        int p = lane & 1;
        int r0 = wm * 32 + p * 16 + (lane >> 2);
        int lu = wn * 8 + ((lane & 3) >> 1);
        int b0 = mh * 128 + r0;

        float hcur[8];
#pragma unroll
        for (int n8 = 0; n8 < 4; n8++) {
            int j = nt * 16 + lu + n8 * 2;
            hcur[n8 * 2]     = hidden[(size_t)b0 * HID + j];
            hcur[n8 * 2 + 1] = hidden[(size_t)(b0 + 8) * HID + j];
        }

        // step 0 (streamed W0, step0 bias set)
        {
            float rb[4], zb[4], nb[4], nhb[4];
#pragma unroll
            for (int n8 = 0; n8 < 4; n8++) {
                int j = nt * 16 + lu + n8 * 2;
                rb[n8]  = bih[j] + bhh[j];
                zb[n8]  = bih[HID + j] + bhh[HID + j];
                nb[n8]  = bih[2 * HID + j];
                nhb[n8] = bhh[2 * HID + j];
            }
            rec_step0(base, nt, mh, tid, rb, zb, nb, nhb, hcur, T > 1);
        }

        if (T > 1) {
            // load resident W (128 KB, once)
            const char* Wsrc = g_Wimg + (size_t)nt * (16 * 8192);
#pragma unroll
            for (int q = 0; q < 32; q++)
                cpa16(base + q * 4096 + tid * 16, Wsrc + q * 4096 + tid * 16);
            CP_COMMIT(); CP_WAIT(0);
            __syncthreads();

            float rb[4], zb[4], nb[4], nhb[4];
#pragma unroll
            for (int n8 = 0; n8 < 4; n8++) {
                int j = nt * 16 + lu + n8 * 2;
                rb[n8]  = g_bcomb[j] + bhh[j];
                zb[n8]  = g_bcomb[HID + j] + bhh[HID + j];
                nb[n8]  = g_bcomb[2 * HID + j];
                nhb[n8] = bhh[2 * HID + j];
            }
            for (int s = 1; s < T; s++)
                rec_step(base, s, nt, mh, tid, rb, zb, nb, nhb, hcur, s + 1 < T);
        }
    }

    // out-tile work queue (all CTAs eventually)
    unsigned total = 12u * (unsigned)T;
    for (;;) {
        __syncthreads();
        if (tid == 0) s_idx = atomicAdd(&g_outq, 1u);
        __syncthreads();
        unsigned idx = s_idx;
        if (idx >= total) break;
        int tt = (int)(idx / 12u) + 1;
        int rem = (int)(idx % 12u);
        int ont = rem % 6, omh = rem / 6;
        unsigned tgt = 8u * (unsigned)tt;
        if (tid < 8) {
            while (ld_acquire(&g_barm8[omh][tid * 32]) < tgt) __nanosleep(128);
        }
        __syncthreads();
        out_tile(base, tt, ont, omh, tid, out, bfc);
    }
}

// ===========================================================================
extern "C" void kernel_launch(void* const* d_in, const int* in_sizes, int n_in,
                              void* d_out, int out_size) {
    const float* src    = (const float*)d_in[0];
    const float* hidden = (const float*)d_in[2];
    const float* W_ih   = (const float*)d_in[3];
    const float* W_hh   = (const float*)d_in[4];
    const float* b_ih   = (const float*)d_in[5];
    const float* b_hh   = (const float*)d_in[6];
    const float* W_fc   = (const float*)d_in[7];
    const float* b_fc   = (const float*)d_in[8];
    float* out = (float*)d_out;

    int T = out_size / (BATCH * OUTD);
    if (T > TMAX) T = TMAX;
    if (T < 1) T = 1;

    float* pbc;
    cudaGetSymbolAddress((void**)&pbc, g_bcomb);

    cudaFuncSetAttribute(uber, cudaFuncAttributeMaxDynamicSharedMemorySize, UBER_DYN);
    cudaFuncSetAttribute(wcomb_gemm, cudaFuncAttributeMaxDynamicSharedMemorySize, 2 * WCG_STG);

    // --- precompute (all HMMA / bandwidth-bound packers) ---
    init_sync<<<1, 1>>>();
    pack_wih_img<<<dim3(24, 12), 256>>>(W_ih);
    pack_wfcT_img<<<dim3(8, 12), 256>>>(W_fc);
    pack_w0img<<<dim3(64, 28), 256>>>(W_ih, W_hh);
    pack_a0img<<<dim3(2, 28), 256>>>(src, hidden);
    pack_wfcimg<<<dim3(6, 16), 256>>>(W_fc);
    bcomb_k<<<(3 * HID) / 8, 256>>>(W_ih, b_fc, b_ih, pbc);
    wcomb_gemm<<<dim3(8, 24), 256, 2 * WCG_STG>>>();
    pack_wimg<<<dim3(64, 16), 256>>>(W_hh);

    // --- über-kernel: step0 + recurrence + work-stealing output projection ---
    uber<<<148, 256, UBER_DYN>>>(T, b_ih, b_hh, hidden, out, b_fc);
}

// round 16
// speedup vs baseline: 1.2920x; 1.0975x over previous
#include <cuda_runtime.h>
#include <cuda_fp16.h>
#include <math.h>
#include <stdint.h>

#define HID   1024
#define OUTD  768
#define BATCH 256
#define TMAX  256

// ===========================================================================
// helpers
// ===========================================================================
__device__ __forceinline__ uint32_t smem_u32(const void* p) {
    uint32_t a;
    asm("{ .reg .u64 t; cvta.to.shared.u64 t, %1; cvt.u32.u64 %0, t; }" : "=r"(a) : "l"(p));
    return a;
}
__device__ __host__ __forceinline__ uint32_t sw128(uint32_t off) {
    return off ^ ((off >> 3) & 0x70);
}
__device__ __forceinline__ void cpa16(uint32_t dst, const void* src) {
    asm volatile("cp.async.cg.shared.global [%0], [%1], 16;" :: "r"(dst), "l"(src));
}
#define CP_COMMIT() asm volatile("cp.async.commit_group;" ::: "memory")
#define CP_WAIT(n)  asm volatile("cp.async.wait_group %0;" :: "n"(n) : "memory")

__device__ __forceinline__ void ldsm4(uint32_t (&r)[4], uint32_t addr) {
    asm volatile("ldmatrix.sync.aligned.m8n8.x4.shared.b16 {%0,%1,%2,%3}, [%4];"
        : "=r"(r[0]), "=r"(r[1]), "=r"(r[2]), "=r"(r[3]) : "r"(addr));
}
__device__ __forceinline__ void mma16816h(float (&d)[4], const uint32_t (&a)[4],
                                          uint32_t b0, uint32_t b1) {
    asm volatile("mma.sync.aligned.m16n8k16.row.col.f32.f16.f16.f32 "
        "{%0,%1,%2,%3}, {%4,%5,%6,%7}, {%8,%9}, {%0,%1,%2,%3};"
        : "+f"(d[0]), "+f"(d[1]), "+f"(d[2]), "+f"(d[3])
        : "r"(a[0]), "r"(a[1]), "r"(a[2]), "r"(a[3]), "r"(b0), "r"(b1));
}

__device__ __forceinline__ unsigned atom_add_release(unsigned* p, unsigned v) {
    unsigned old;
    asm volatile("atom.release.gpu.global.add.u32 %0, [%1], %2;"
        : "=r"(old) : "l"(p), "r"(v) : "memory");
    return old;
}
__device__ __forceinline__ unsigned ld_acquire(const unsigned* p) {
    unsigned v;
    asm volatile("ld.acquire.gpu.global.u32 %0, [%1];" : "=r"(v) : "l"(p) : "memory");
    return v;
}

// ===========================================================================
// device scratch
// ===========================================================================
__device__ float g_Wc[3 * HID * HID];               // fp32 W_comb
__device__ float g_bcomb[3 * HID];
__device__ unsigned g_barm8[2][8 * 32];             // per-mh, 8 split arrival counters
__device__ unsigned g_outq;
// fp16 SW128 images
__device__ __align__(1024) char g_Aimg[(size_t)(TMAX + 1) * 2 * 16 * 16384]; // [t][mh][kc16] 128x64
__device__ __align__(1024) char g_Wimg[(size_t)64 * 16 * 8192];              // rec W single fp16 [nt][kc16] 64x64
__device__ __align__(1024) char g_Wfcimg[(size_t)6 * 16 * 16384];            // out W SINGLE fp16 [nt][kc16] 128x64
__device__ __align__(1024) char g_WihImg[(size_t)24 * 12 * 32768];           // W_ih hi/lo [mt][kb12] 128x64
__device__ __align__(1024) char g_WfcTImg[(size_t)8 * 12 * 32768];           // W_fc^T hi/lo [nt][kb12] 128x64
__device__ __align__(1024) char g_W0img[(size_t)64 * 28 * 8192];             // step0 W single fp16 [nt][kb28] 64x64
__device__ __align__(1024) char g_A0img[(size_t)2 * 28 * 16384];             // step0 A [mh][kb28] 128x64

// ===========================================================================
// fp16 split + packers
// ===========================================================================
union BPK { unsigned short s[8]; uint4 v; };
__device__ __forceinline__ void split8h(const float* v, uint4& hi, uint4& lo) {
    BPK ph, pl;
#pragma unroll
    for (int i = 0; i < 8; i++) {
        __half a = __float2half(v[i]);
        float r = v[i] - __half2float(a);
        __half b = __float2half(r);
        ph.s[i] = *(unsigned short*)&a;
        pl.s[i] = *(unsigned short*)&b;
    }
    hi = ph.v; lo = pl.v;
}
__device__ __forceinline__ uint4 cvt8h(const float* v) {
    BPK p;
#pragma unroll
    for (int i = 0; i < 8; i++) {
        __half a = __float2half(v[i]);
        p.s[i] = *(unsigned short*)&a;
    }
    return p.v;
}

__global__ __launch_bounds__(256) void bcomb_k(const float* __restrict__ Wih,
                                               const float* __restrict__ bfc,
                                               const float* __restrict__ bih,
                                               float* __restrict__ out) {
    int j = blockIdx.x * 8 + (threadIdx.x >> 5);
    int lane = threadIdx.x & 31;
    float s = 0.f;
    for (int o = lane; o < OUTD; o += 32) s += Wih[(size_t)j * OUTD + o] * bfc[o];
#pragma unroll
    for (int off = 16; off; off >>= 1) s += __shfl_xor_sync(0xffffffffu, s, off);
    if (lane == 0) out[j] = s + bih[j];
}

__global__ void init_sync() {
    for (int m = 0; m < 2; m++)
        for (int s = 0; s < 8; s++) g_barm8[m][s * 32] = 0;
    g_outq = 0;
}

// W_ih [3072 x 768] -> hi/lo blocks [mt 24][kb 12]
__global__ __launch_bounds__(256) void pack_wih_img(const float* __restrict__ Wih) {
    int mt = blockIdx.x, kb = blockIdx.y, tid = threadIdx.x;
    char* dst = g_WihImg + ((size_t)mt * 12 + kb) * 32768;
    for (int u = tid; u < 1024; u += 256) {
        int r = u >> 3, unit = u & 7;
        const float* s = Wih + (size_t)(mt * 128 + r) * OUTD + kb * 64 + unit * 8;
        float v[8];
        *(float4*)&v[0] = *(const float4*)s;
        *(float4*)&v[4] = *(const float4*)(s + 4);
        uint4 hi, lo; split8h(v, hi, lo);
        uint32_t o = sw128((uint32_t)(r * 128 + unit * 16));
        *(uint4*)(dst + o) = hi;
        *(uint4*)(dst + 16384 + o) = lo;
    }
}

// W_fc^T: B[n][k] = W_fc[k][n]  -> hi/lo blocks [nt 8][kb 12]
__global__ __launch_bounds__(256) void pack_wfcT_img(const float* __restrict__ Wfc) {
    int nt = blockIdx.x, kb = blockIdx.y, tid = threadIdx.x;
    char* dst = g_WfcTImg + ((size_t)nt * 12 + kb) * 32768;
    for (int u = tid; u < 1024; u += 256) {
        int r = u >> 3, unit = u & 7;
        int n = nt * 128 + r;
        int k0 = kb * 64 + unit * 8;
        float v[8];
#pragma unroll
        for (int i = 0; i < 8; i++) v[i] = Wfc[(size_t)(k0 + i) * HID + n];
        uint4 hi, lo; split8h(v, hi, lo);
        uint32_t o = sw128((uint32_t)(r * 128 + unit * 16));
        *(uint4*)(dst + o) = hi;
        *(uint4*)(dst + 16384 + o) = lo;
    }
}

// HMMA W_comb: g_Wc[3072][1024] = W_ih @ W_fc  (3-product hi/lo)
#define WCG_STG 65536
__global__ __launch_bounds__(256, 1) void wcomb_gemm() {
    extern __shared__ char dsm[];
    uint32_t base = smem_u32(dsm);
    int tid = threadIdx.x, wid = tid >> 5, lane = tid & 31;
    int nt = blockIdx.x, mt = blockIdx.y;
    int wm = wid & 1, wn = wid >> 1;
    const char* Asrc = g_WihImg + (size_t)mt * (12 * 32768);
    const char* Bsrc = g_WfcTImg + (size_t)nt * (12 * 32768);

    float acc[4][4][4];
#pragma unroll
    for (int a = 0; a < 4; a++)
#pragma unroll
        for (int b = 0; b < 4; b++)
#pragma unroll
            for (int c = 0; c < 4; c++) acc[a][b][c] = 0.f;

    {
#pragma unroll
        for (int q = 0; q < 8; q++) {
            cpa16(base + q * 4096 + tid * 16, Asrc + q * 4096 + tid * 16);
            cpa16(base + 32768 + q * 4096 + tid * 16, Bsrc + q * 4096 + tid * 16);
        }
        CP_COMMIT();
    }
    for (int c = 0; c < 12; c++) {
        if (c < 11) {
            uint32_t d = base + ((c + 1) & 1) * WCG_STG;
#pragma unroll
            for (int q = 0; q < 8; q++) {
                cpa16(d + q * 4096 + tid * 16, Asrc + (size_t)(c + 1) * 32768 + q * 4096 + tid * 16);
                cpa16(d + 32768 + q * 4096 + tid * 16, Bsrc + (size_t)(c + 1) * 32768 + q * 4096 + tid * 16);
            }
            CP_COMMIT();
            CP_WAIT(1);
        } else {
            CP_WAIT(0);
        }
        __syncthreads();
        uint32_t sA = base + (c & 1) * WCG_STG;
        uint32_t sB = sA + 32768;
#pragma unroll
        for (int kk = 0; kk < 4; kk++) {
            uint32_t ah[4][4], al[4][4], bh[2][4], bl[2][4];
            int seg = kk * 32 + (lane >> 4) * 16;
#pragma unroll
            for (int m4 = 0; m4 < 4; m4++) {
                int r = wm * 64 + m4 * 16 + (lane & 15);
                uint32_t off = sw128((uint32_t)(r * 128 + seg));
                ldsm4(ah[m4], sA + off);
                ldsm4(al[m4], sA + 16384 + off);
            }
#pragma unroll
            for (int nq = 0; nq < 2; nq++) {
                int r = wn * 32 + nq * 16 + (lane & 15);
                uint32_t off = sw128((uint32_t)(r * 128 + seg));
                ldsm4(bh[nq], sB + off);
                ldsm4(bl[nq], sB + 16384 + off);
            }
#pragma unroll
            for (int m4 = 0; m4 < 4; m4++)
#pragma unroll
                for (int n8 = 0; n8 < 4; n8++) {
                    int nq = n8 >> 1, hf = n8 & 1;
                    mma16816h(acc[m4][n8], ah[m4], bh[nq][hf], bh[nq][hf + 2]);
                    mma16816h(acc[m4][n8], ah[m4], bl[nq][hf], bl[nq][hf + 2]);
                    mma16816h(acc[m4][n8], al[m4], bh[nq][hf], bh[nq][hf + 2]);
                }
        }
        __syncthreads();
    }
#pragma unroll
    for (int m4 = 0; m4 < 4; m4++)
#pragma unroll
        for (int n8 = 0; n8 < 4; n8++) {
            int m = mt * 128 + wm * 64 + m4 * 16 + (lane >> 2);
            int n = nt * 128 + wn * 32 + n8 * 8 + 2 * (lane & 3);
            *(float2*)&g_Wc[(size_t)m * HID + n]       = make_float2(acc[m4][n8][0], acc[m4][n8][1]);
            *(float2*)&g_Wc[(size_t)(m + 8) * HID + n] = make_float2(acc[m4][n8][2], acc[m4][n8][3]);
        }
}

// Gate-fused rec W image (single fp16): [nt 64][kc 16] 64 rows x 64 k
__global__ __launch_bounds__(256) void pack_wimg(const float* __restrict__ Whh) {
    int nt = blockIdx.x, kc = blockIdx.y, tid = threadIdx.x;
    char* dst = g_Wimg + ((size_t)nt * 16 + kc) * 8192;
    for (int u = tid; u < 512; u += 256) {
        int r = u >> 3, unit = u & 7;
        int jt = r >> 2, c = r & 3;
        int j = nt * 16 + jt;
        float v[8];
        if (c < 2) {
            const float* s1 = g_Wc + (size_t)(c * HID + j) * HID + kc * 64 + unit * 8;
            const float* s2 = Whh  + (size_t)(c * HID + j) * HID + kc * 64 + unit * 8;
            float4 a0 = *(const float4*)s1, a1 = *(const float4*)(s1 + 4);
            float4 b0 = *(const float4*)s2, b1 = *(const float4*)(s2 + 4);
            v[0] = a0.x + b0.x; v[1] = a0.y + b0.y; v[2] = a0.z + b0.z; v[3] = a0.w + b0.w;
            v[4] = a1.x + b1.x; v[5] = a1.y + b1.y; v[6] = a1.z + b1.z; v[7] = a1.w + b1.w;
        } else {
            const float* s1 = (c == 2 ? g_Wc : Whh) + (size_t)(2 * HID + j) * HID + kc * 64 + unit * 8;
            *(float4*)&v[0] = *(const float4*)s1;
            *(float4*)&v[4] = *(const float4*)(s1 + 4);
        }
        uint32_t o = sw128((uint32_t)(r * 128 + unit * 16));
        *(uint4*)(dst + o) = cvt8h(v);
    }
}

// Step0 W image (single fp16, concat K=1792, zero-padded n-gate cols): [nt 64][kb 28]
__global__ __launch_bounds__(256) void pack_w0img(const float* __restrict__ Wih,
                                                  const float* __restrict__ Whh) {
    int nt = blockIdx.x, kb = blockIdx.y, tid = threadIdx.x;
    char* dst = g_W0img + ((size_t)nt * 28 + kb) * 8192;
    for (int u = tid; u < 512; u += 256) {
        int r = u >> 3, unit = u & 7;
        int jt = r >> 2, c = r & 3;
        int j = nt * 16 + jt;
        float v[8] = {0, 0, 0, 0, 0, 0, 0, 0};
        if (kb < 12) {
            int k0 = kb * 64 + unit * 8;
            if (c < 3) {
                const float* s = Wih + (size_t)(c * HID + j) * OUTD + k0;
                *(float4*)&v[0] = *(const float4*)s;
                *(float4*)&v[4] = *(const float4*)(s + 4);
            }
        } else {
            int k0 = kb * 64 - 768 + unit * 8;
            if (c != 2) {
                int g = (c == 3) ? 2 : c;
                const float* s = Whh + (size_t)(g * HID + j) * HID + k0;
                *(float4*)&v[0] = *(const float4*)s;
                *(float4*)&v[4] = *(const float4*)(s + 4);
            }
        }
        uint32_t o = sw128((uint32_t)(r * 128 + unit * 16));
        *(uint4*)(dst + o) = cvt8h(v);
    }
}

// Step0 A image: concat [x0 | h0] fp16: [mh 2][kb 28]
__global__ __launch_bounds__(256) void pack_a0img(const float* __restrict__ src,
                                                  const float* __restrict__ hidden) {
    int mh = blockIdx.x, kb = blockIdx.y, tid = threadIdx.x;
    char* dst = g_A0img + ((size_t)mh * 28 + kb) * 16384;
    for (int u = tid; u < 1024; u += 256) {
        int r = u >> 3, unit = u & 7;
        int b = mh * 128 + r;
        float v[8];
        if (kb < 12) {
            const float* s = src + (size_t)b * OUTD + kb * 64 + unit * 8;
            *(float4*)&v[0] = *(const float4*)s;
            *(float4*)&v[4] = *(const float4*)(s + 4);
        } else {
            const float* s = hidden + (size_t)b * HID + kb * 64 - 768 + unit * 8;
            *(float4*)&v[0] = *(const float4*)s;
            *(float4*)&v[4] = *(const float4*)(s + 4);
        }
        uint32_t o = sw128((uint32_t)(r * 128 + unit * 16));
        *(uint4*)(dst + o) = cvt8h(v);
    }
}

// Out-projection W_fc image (SINGLE fp16): [nt 6][kc 16] 128 rows x 64 k (16KB blocks)
__global__ __launch_bounds__(256) void pack_wfcimg(const float* __restrict__ Wfc) {
    int nt = blockIdx.x, kc = blockIdx.y, tid = threadIdx.x;
    char* dst = g_Wfcimg + ((size_t)nt * 16 + kc) * 16384;
    for (int u = tid; u < 1024; u += 256) {
        int r = u >> 3, unit = u & 7;
        const float* srcrow = Wfc + (size_t)(nt * 128 + r) * HID + kc * 64 + unit * 8;
        float v[8];
        *(float4*)&v[0] = *(const float4*)srcrow;
        *(float4*)&v[4] = *(const float4*)(srcrow + 4);
        uint32_t o = sw128((uint32_t)(r * 128 + unit * 16));
        *(uint4*)(dst + o) = cvt8h(v);
    }
}

// ===========================================================================
// über-kernel
// ===========================================================================
#define WRES 131072
#define RSTG 32768
#define OSTG 65536   // A 32K + Bfc single 32K (2 kc-blocks of 16KB per K=128 chunk)
#define UBER_DYN 229376

__device__ __forceinline__ float fast_tanh(float x) {
    float e = __expf(-2.f * x);
    return __fdividef(1.f - e, 1.f + e);
}
__device__ __forceinline__ float fast_sig(float x) {
    return __fdividef(1.f, 1.f + __expf(-x));
}

__device__ __forceinline__ void gru_epilogue(float (&acc)[2][4][4], float (&hcur)[8],
                                             const float (&rb)[4], const float (&zb)[4],
                                             const float (&nb)[4], const float (&nhb)[4],
                                             int s, int nt, int mh, int tid, bool waitNext) {
    int wid = tid >> 5, lane = tid & 31;
    int wm = wid & 3, wn = wid >> 2;
    int p = lane & 1;
#pragma unroll
    for (int n8 = 0; n8 < 4; n8++) {
        float s0 = p ? acc[0][n8][0] : acc[1][n8][0];
        float s1 = p ? acc[0][n8][1] : acc[1][n8][1];
        float s2 = p ? acc[0][n8][2] : acc[1][n8][2];
        float s3 = p ? acc[0][n8][3] : acc[1][n8][3];
        float o0 = __shfl_xor_sync(0xffffffffu, s0, 1);
        float o1 = __shfl_xor_sync(0xffffffffu, s1, 1);
        float o2 = __shfl_xor_sync(0xffffffffu, s2, 1);
        float o3 = __shfl_xor_sync(0xffffffffu, s3, 1);
        float rz0 = p ? o0 : acc[0][n8][0];
        float rz1 = p ? o1 : acc[0][n8][1];
        float rz2 = p ? o2 : acc[0][n8][2];
        float rz3 = p ? o3 : acc[0][n8][3];
        float nh0 = p ? acc[1][n8][0] : o0;
        float nh1 = p ? acc[1][n8][1] : o1;
        float nh2 = p ? acc[1][n8][2] : o2;
        float nh3 = p ? acc[1][n8][3] : o3;
        float rg = fast_sig(rz0 + rb[n8]);
        float zg = fast_sig(rz1 + zb[n8]);
        float ng = fast_tanh(nh0 + nb[n8] + rg * (nh1 + nhb[n8]));
        hcur[n8 * 2]     = (1.f - zg) * ng + zg * hcur[n8 * 2];
        rg = fast_sig(rz2 + rb[n8]);
        zg = fast_sig(rz3 + zb[n8]);
        ng = fast_tanh(nh2 + nb[n8] + rg * (nh3 + nhb[n8]));
        hcur[n8 * 2 + 1] = (1.f - zg) * ng + zg * hcur[n8 * 2 + 1];
    }
    {
        int r0 = wm * 32 + p * 16 + (lane >> 2);
        int lu = wn * 8 + ((lane & 3) >> 1);
        char* dst = g_Aimg + ((size_t)((s + 1) * 2 + mh) * 16 + (nt >> 2)) * 16384;
        uint32_t cbase = (uint32_t)((nt & 3) * 32 + lu * 2);
#pragma unroll
        for (int n8 = 0; n8 < 4; n8++) {
            __half h0 = __float2half(hcur[n8 * 2]);
            __half h1 = __float2half(hcur[n8 * 2 + 1]);
            uint32_t off0 = (uint32_t)(r0 * 128) + cbase + (uint32_t)(n8 * 4);
            *(unsigned short*)(dst + sw128(off0)) = *(unsigned short*)&h0;
            *(unsigned short*)(dst + sw128(off0 + 8 * 128)) = *(unsigned short*)&h1;
        }
    }
    __syncthreads();
    if (tid == 0) atom_add_release(&g_barm8[mh][(nt & 7) * 32], 1u);
    if (waitNext && tid < 8) {
        unsigned tgt = 8u * (unsigned)(s + 1);
        while (ld_acquire(&g_barm8[mh][tid * 32]) < tgt) __nanosleep(32);
    }
    __syncthreads();
}

__device__ __forceinline__ void rec_step(uint32_t base, int s, int nt, int mh,
                                         int tid, const float (&rb)[4],
                                         const float (&zb)[4],
                                         const float (&nb)[4],
                                         const float (&nhb)[4],
                                         float (&hcur)[8], bool waitNext) {
    int wid = tid >> 5, lane = tid & 31;
    int wm = wid & 3, wn = wid >> 2;
    const char* Asrc = g_Aimg + (size_t)(s * 2 + mh) * (16 * 16384);
    uint32_t aBase = base + WRES;

    float acc[2][4][4];
#pragma unroll
    for (int a = 0; a < 2; a++)
#pragma unroll
        for (int b = 0; b < 4; b++)
#pragma unroll
            for (int cc = 0; cc < 4; cc++) acc[a][b][cc] = 0.f;

#pragma unroll
    for (int pc = 0; pc < 2; pc++) {
        uint32_t d = aBase + pc * RSTG;
#pragma unroll
        for (int q = 0; q < 8; q++)
            cpa16(d + q * 4096 + tid * 16, Asrc + (size_t)pc * 32768 + q * 4096 + tid * 16);
        CP_COMMIT();
    }

    for (int c = 0; c < 8; c++) {
        if (c == 7) { CP_WAIT(0); } else { CP_WAIT(1); }
        __syncthreads();
        if (c + 2 < 8) {
            uint32_t d = aBase + ((c + 2) % 3) * RSTG;
#pragma unroll
            for (int q = 0; q < 8; q++)
                cpa16(d + q * 4096 + tid * 16, Asrc + (size_t)(c + 2) * 32768 + q * 4096 + tid * 16);
            CP_COMMIT();
        }
        uint32_t sA = aBase + (c % 3) * RSTG;
        uint32_t sW = base + c * 16384;
#pragma unroll
        for (int kk = 0; kk < 8; kk++) {
            uint32_t ah[2][4], bh[2][4];
            int blk = kk >> 2;
            int seg = (kk & 3) * 32 + (lane >> 4) * 16;
#pragma unroll
            for (int mt = 0; mt < 2; mt++) {
                int r = wm * 32 + mt * 16 + (lane & 15);
                ldsm4(ah[mt], sA + blk * 16384 + sw128((uint32_t)(r * 128 + seg)));
            }
#pragma unroll
            for (int nq = 0; nq < 2; nq++) {
                int r = wn * 32 + nq * 16 + (lane & 15);
                ldsm4(bh[nq], sW + blk * 8192 + sw128((uint32_t)(r * 128 + seg)));
            }
#pragma unroll
            for (int mt = 0; mt < 2; mt++)
#pragma unroll
                for (int n8 = 0; n8 < 4; n8++) {
                    int nq = n8 >> 1, hf = n8 & 1;
                    mma16816h(acc[mt][n8], ah[mt], bh[nq][hf], bh[nq][hf + 2]);
                }
        }
    }
    gru_epilogue(acc, hcur, rb, zb, nb, nhb, s, nt, mh, tid, waitNext);
}

// step 0: streamed W0 (K=1792 concat [x0|h0]), writes image 1
__device__ __forceinline__ void rec_step0(uint32_t base, int nt, int mh, int tid,
                                          const float (&rb)[4], const float (&zb)[4],
                                          const float (&nb)[4], const float (&nhb)[4],
                                          float (&hcur)[8], bool waitNext) {
    int wid = tid >> 5, lane = tid & 31;
    int wm = wid & 3, wn = wid >> 2;
    const char* Asrc = g_A0img + (size_t)mh * (28 * 16384);
    const char* Wsrc = g_W0img + (size_t)nt * (28 * 8192);
    uint32_t aBase = base + WRES;

    float acc[2][4][4];
#pragma unroll
    for (int a = 0; a < 2; a++)
#pragma unroll
        for (int b = 0; b < 4; b++)
#pragma unroll
            for (int cc = 0; cc < 4; cc++) acc[a][b][cc] = 0.f;

#pragma unroll
    for (int pc = 0; pc < 2; pc++) {
        uint32_t dA = aBase + pc * RSTG;
        uint32_t dW = base + pc * 16384;
#pragma unroll
        for (int q = 0; q < 8; q++)
            cpa16(dA + q * 4096 + tid * 16, Asrc + (size_t)pc * 32768 + q * 4096 + tid * 16);
#pragma unroll
        for (int q = 0; q < 4; q++)
            cpa16(dW + q * 4096 + tid * 16, Wsrc + (size_t)pc * 16384 + q * 4096 + tid * 16);
        CP_COMMIT();
    }

    for (int c = 0; c < 14; c++) {
        if (c == 13) { CP_WAIT(0); } else { CP_WAIT(1); }
        __syncthreads();
        if (c + 2 < 14) {
            uint32_t dA = aBase + ((c + 2) % 3) * RSTG;
            uint32_t dW = base + ((c + 2) % 3) * 16384;
#pragma unroll
            for (int q = 0; q < 8; q++)
                cpa16(dA + q * 4096 + tid * 16, Asrc + (size_t)(c + 2) * 32768 + q * 4096 + tid * 16);
#pragma unroll
            for (int q = 0; q < 4; q++)
                cpa16(dW + q * 4096 + tid * 16, Wsrc + (size_t)(c + 2) * 16384 + q * 4096 + tid * 16);
            CP_COMMIT();
        }
        uint32_t sA = aBase + (c % 3) * RSTG;
        uint32_t sW = base + (c % 3) * 16384;
#pragma unroll
        for (int kk = 0; kk < 8; kk++) {
            uint32_t ah[2][4], bh[2][4];
            int blk = kk >> 2;
            int seg = (kk & 3) * 32 + (lane >> 4) * 16;
#pragma unroll
            for (int mt = 0; mt < 2; mt++) {
                int r = wm * 32 + mt * 16 + (lane & 15);
                ldsm4(ah[mt], sA + blk * 16384 + sw128((uint32_t)(r * 128 + seg)));
            }
#pragma unroll
            for (int nq = 0; nq < 2; nq++) {
                int r = wn * 32 + nq * 16 + (lane & 15);
                ldsm4(bh[nq], sW + blk * 8192 + sw128((uint32_t)(r * 128 + seg)));
            }
#pragma unroll
            for (int mt = 0; mt < 2; mt++)
#pragma unroll
                for (int n8 = 0; n8 < 4; n8++) {
                    int nq = n8 >> 1, hf = n8 & 1;
                    mma16816h(acc[mt][n8], ah[mt], bh[nq][hf], bh[nq][hf + 2]);
                }
        }
    }
    gru_epilogue(acc, hcur, rb, zb, nb, nhb, 0, nt, mh, tid, waitNext);
}

// out tile: single fp16 W_fc, one product.  Chunk = K=128 = 2 kc-blocks (32KB).
__device__ __forceinline__ void out_tile(uint32_t base, int tt, int ont, int omh,
                                         int tid, float* __restrict__ out,
                                         const float* __restrict__ bfc) {
    int wid = tid >> 5, lane = tid & 31;
    int wm = wid & 1, wn = wid >> 1;
    const char* Asrc = g_Aimg + (size_t)(tt * 2 + omh) * (16 * 16384);
    const char* Bsrc = g_Wfcimg + (size_t)ont * (16 * 16384);

    float acc[4][4][4];
#pragma unroll
    for (int a = 0; a < 4; a++)
#pragma unroll
        for (int b = 0; b < 4; b++)
#pragma unroll
            for (int cc = 0; cc < 4; cc++) acc[a][b][cc] = 0.f;

    {
#pragma unroll
        for (int q = 0; q < 8; q++) {
            cpa16(base + q * 4096 + tid * 16, Asrc + q * 4096 + tid * 16);
            cpa16(base + 32768 + q * 4096 + tid * 16, Bsrc + q * 4096 + tid * 16);
        }
        CP_COMMIT();
    }

    for (int c = 0; c < 8; c++) {
        if (c < 7) {
            uint32_t d = base + ((c + 1) & 1) * OSTG;
#pragma unroll
            for (int q = 0; q < 8; q++) {
                cpa16(d + q * 4096 + tid * 16, Asrc + (size_t)(c + 1) * 32768 + q * 4096 + tid * 16);
                cpa16(d + 32768 + q * 4096 + tid * 16, Bsrc + (size_t)(c + 1) * 32768 + q * 4096 + tid * 16);
            }
            CP_COMMIT();
            CP_WAIT(1);
        } else {
            CP_WAIT(0);
        }
        __syncthreads();
        uint32_t sA = base + (c & 1) * OSTG;
        uint32_t sB = sA + 32768;
#pragma unroll
        for (int kk = 0; kk < 8; kk++) {
            uint32_t ah[4][4], bh[2][4];
            int blk = kk >> 2;
            int seg = (kk & 3) * 32 + (lane >> 4) * 16;
#pragma unroll
            for (int mt = 0; mt < 4; mt++) {
                int r = wm * 64 + mt * 16 + (lane & 15);
                ldsm4(ah[mt], sA + blk * 16384 + sw128((uint32_t)(r * 128 + seg)));
            }
#pragma unroll
            for (int nq = 0; nq < 2; nq++) {
                int r = wn * 32 + nq * 16 + (lane & 15);
                ldsm4(bh[nq], sB + blk * 16384 + sw128((uint32_t)(r * 128 + seg)));
            }
#pragma unroll
            for (int mt = 0; mt < 4; mt++)
#pragma unroll
                for (int n8 = 0; n8 < 4; n8++) {
                    int nq = n8 >> 1, hf = n8 & 1;
                    mma16816h(acc[mt][n8], ah[mt], bh[nq][hf], bh[nq][hf + 2]);
                }
        }
        __syncthreads();
    }

    size_t row0 = (size_t)(tt - 1) * BATCH + omh * 128;
#pragma unroll
    for (int mt = 0; mt < 4; mt++)
#pragma unroll
        for (int n8 = 0; n8 < 4; n8++) {
            int rr = wm * 64 + mt * 16 + (lane >> 2);
            int cc = ont * 128 + wn * 32 + n8 * 8 + 2 * (lane & 3);
            float2 bv = *(const float2*)(bfc + cc);
            float2 v0 = make_float2(acc[mt][n8][0] + bv.x, acc[mt][n8][1] + bv.y);
            float2 v1 = make_float2(acc[mt][n8][2] + bv.x, acc[mt][n8][3] + bv.y);
            *(float2*)(out + (row0 + rr) * OUTD + cc)     = v0;
            *(float2*)(out + (row0 + rr + 8) * OUTD + cc) = v1;
        }
}

__global__ __launch_bounds__(256, 1) void uber(int T, const float* __restrict__ bih,
                                               const float* __restrict__ bhh,
                                               const float* __restrict__ hidden,
                                               float* __restrict__ out,
                                               const float* __restrict__ bfc) {
    extern __shared__ char dsm[];
    __shared__ unsigned s_idx;
    uint32_t base = smem_u32(dsm);
    int bid = blockIdx.x, tid = threadIdx.x;

    if (bid < 128) {
        int nt = bid >> 1, mh = bid & 1;
        int wid = tid >> 5, lane = tid & 31;
        int wm = wid & 3, wn = wid >> 2;
        int p = lane & 1;
        int r0 = wm * 32 + p * 16 + (lane >> 2);
        int lu = wn * 8 + ((lane & 3) >> 1);
        int b0 = mh * 128 + r0;

        float hcur[8];
#pragma unroll
        for (int n8 = 0; n8 < 4; n8++) {
            int j = nt * 16 + lu + n8 * 2;
            hcur[n8 * 2]     = hidden[(size_t)b0 * HID + j];
            hcur[n8 * 2 + 1] = hidden[(size_t)(b0 + 8) * HID + j];
        }

        {
            float rb[4], zb[4], nb[4], nhb[4];
#pragma unroll
            for (int n8 = 0; n8 < 4; n8++) {
                int j = nt * 16 + lu + n8 * 2;
                rb[n8]  = bih[j] + bhh[j];
                zb[n8]  = bih[HID + j] + bhh[HID + j];
                nb[n8]  = bih[2 * HID + j];
                nhb[n8] = bhh[2 * HID + j];
            }
            rec_step0(base, nt, mh, tid, rb, zb, nb, nhb, hcur, T > 1);
        }

        if (T > 1) {
            const char* Wsrc = g_Wimg + (size_t)nt * (16 * 8192);
#pragma unroll
            for (int q = 0; q < 32; q++)
                cpa16(base + q * 4096 + tid * 16, Wsrc + q * 4096 + tid * 16);
            CP_COMMIT(); CP_WAIT(0);
            __syncthreads();

            float rb[4], zb[4], nb[4], nhb[4];
#pragma unroll
            for (int n8 = 0; n8 < 4; n8++) {
                int j = nt * 16 + lu + n8 * 2;
                rb[n8]  = g_bcomb[j] + bhh[j];
                zb[n8]  = g_bcomb[HID + j] + bhh[HID + j];
                nb[n8]  = g_bcomb[2 * HID + j];
                nhb[n8] = bhh[2 * HID + j];
            }
            for (int s = 1; s < T; s++)
                rec_step(base, s, nt, mh, tid, rb, zb, nb, nhb, hcur, s + 1 < T);
        }
    }

    // out-tile work queue
    unsigned total = 12u * (unsigned)T;
    for (;;) {
        __syncthreads();
        if (tid == 0) s_idx = atomicAdd(&g_outq, 1u);
        __syncthreads();
        unsigned idx = s_idx;
        if (idx >= total) break;
        int tt = (int)(idx / 12u) + 1;
        int rem = (int)(idx % 12u);
        int ont = rem % 6, omh = rem / 6;
        unsigned tgt = 8u * (unsigned)tt;
        if (tid < 8) {
            while (ld_acquire(&g_barm8[omh][tid * 32]) < tgt) __nanosleep(128);
        }
        __syncthreads();
        out_tile(base, tt, ont, omh, tid, out, bfc);
    }
}

// ===========================================================================
extern "C" void kernel_launch(void* const* d_in, const int* in_sizes, int n_in,
                              void* d_out, int out_size) {
    const float* src    = (const float*)d_in[0];
    const float* hidden = (const float*)d_in[2];
    const float* W_ih   = (const float*)d_in[3];
    const float* W_hh   = (const float*)d_in[4];
    const float* b_ih   = (const float*)d_in[5];
    const float* b_hh   = (const float*)d_in[6];
    const float* W_fc   = (const float*)d_in[7];
    const float* b_fc   = (const float*)d_in[8];
    float* out = (float*)d_out;

    int T = out_size / (BATCH * OUTD);
    if (T > TMAX) T = TMAX;
    if (T < 1) T = 1;

    float* pbc;
    cudaGetSymbolAddress((void**)&pbc, g_bcomb);

    cudaFuncSetAttribute(uber, cudaFuncAttributeMaxDynamicSharedMemorySize, UBER_DYN);
    cudaFuncSetAttribute(wcomb_gemm, cudaFuncAttributeMaxDynamicSharedMemorySize, 2 * WCG_STG);

    // --- precompute ---
    init_sync<<<1, 1>>>();
    pack_wih_img<<<dim3(24, 12), 256>>>(W_ih);
    pack_wfcT_img<<<dim3(8, 12), 256>>>(W_fc);
    pack_w0img<<<dim3(64, 28), 256>>>(W_ih, W_hh);
    pack_a0img<<<dim3(2, 28), 256>>>(src, hidden);
    pack_wfcimg<<<dim3(6, 16), 256>>>(W_fc);
    bcomb_k<<<(3 * HID) / 8, 256>>>(W_ih, b_fc, b_ih, pbc);
    wcomb_gemm<<<dim3(8, 24), 256, 2 * WCG_STG>>>();
    pack_wimg<<<dim3(64, 16), 256>>>(W_hh);

    // --- über-kernel ---
    uber<<<148, 256, UBER_DYN>>>(T, b_ih, b_hh, hidden, out, b_fc);
}